// round 1
// baseline (speedup 1.0000x reference)
#include <cuda_runtime.h>
#include <cmath>

#define D_MODEL 512
#define SEQ     1024
#define NB      8
#define NHEADS  8
#define DHEAD   64
#define FF      2048
#define NROWS   (NB*SEQ)    /* 8192 */
#define NDEPTH  3

// ---------------- scratch (device globals; no allocation allowed) ----------
__device__ float g_x   [NROWS * D_MODEL];          // 16 MB
__device__ float g_h   [NROWS * D_MODEL];          // 16 MB
__device__ float g_qkv [NROWS * 3 * D_MODEL];      // 48 MB
__device__ float g_sim [67108864];                  // 64*1024*1024 = 256 MB
__device__ float g_ao  [NROWS * D_MODEL];          // 16 MB
__device__ float g_hh  [NROWS * 2 * FF];           // 128 MB
__device__ float g_ffg [NROWS * FF];               // 64 MB
__device__ float g_pool[NB * 8 * D_MODEL];         // partial pool sums

// ---------------------------------------------------------------------------
// Generic tiled GEMM:  C[M,N] = alpha * A[M,K] @ op(B) + bias + resid + pos
//   TRANSB=false: B is [K,N] row-major (ldb = row stride)
//   TRANSB=true:  B is [N,K] row-major; computes A @ B^T
// Batched via blockIdx.z: z -> (zo = z>>3, zi = z&7); each operand offset by
// zo*outerStride + zi*innerStride. Unbatched launches use batches=1 (z=0).
// Requires: M%64==0, N%64==0, K%16==0 (true for every call here).
// ---------------------------------------------------------------------------
template<bool TRANSB>
__global__ void __launch_bounds__(256)
gemm_kernel(const float* __restrict__ A, int lda, long aO, long aI,
            const float* __restrict__ B, int ldb, long bO, long bI,
            float* __restrict__ C, int ldc, long cO, long cI,
            int K,
            const float* __restrict__ bias,
            const float* __restrict__ resid,
            const float* __restrict__ pos,
            float alpha)
{
    __shared__ float As[16][68];
    __shared__ float Bs[16][68];

    const int z  = blockIdx.z;
    const int zo = z >> 3, zi = z & 7;
    A += zo * aO + zi * aI;
    B += zo * bO + zi * bI;
    C += zo * cO + zi * cI;

    const int m0 = blockIdx.y * 64;
    const int n0 = blockIdx.x * 64;
    const int t  = threadIdx.x;
    const int tx = t & 15, ty = t >> 4;

    // A tile load mapping: 64 rows x 16 k, one float4 per thread
    const int ar = t >> 2;        // 0..63
    const int ak = (t & 3) * 4;   // 0,4,8,12
    const float* Ag = A + (long)(m0 + ar) * lda + ak;

    const float* Bg;
    if (TRANSB) {
        Bg = B + (long)(n0 + ar) * ldb + ak;        // row = n, cols = k
    } else {
        Bg = B + (long)(t >> 4) * ldb + n0 + (t & 15) * 4;  // 16 rows x 64 n
    }

    float acc[4][4] = {};

    for (int kt = 0; kt < K; kt += 16) {
        float4 av = *(const float4*)(Ag + kt);
        As[ak + 0][ar] = av.x; As[ak + 1][ar] = av.y;
        As[ak + 2][ar] = av.z; As[ak + 3][ar] = av.w;
        if (TRANSB) {
            float4 bv = *(const float4*)(Bg + kt);
            Bs[ak + 0][ar] = bv.x; Bs[ak + 1][ar] = bv.y;
            Bs[ak + 2][ar] = bv.z; Bs[ak + 3][ar] = bv.w;
        } else {
            float4 bv = *(const float4*)(Bg + (long)kt * ldb);
            *(float4*)&Bs[t >> 4][(t & 15) * 4] = bv;
        }
        __syncthreads();
#pragma unroll
        for (int k = 0; k < 16; ++k) {
            float4 a4 = *(const float4*)&As[k][ty * 4];
            float4 b4 = *(const float4*)&Bs[k][tx * 4];
            float a[4] = {a4.x, a4.y, a4.z, a4.w};
            float b[4] = {b4.x, b4.y, b4.z, b4.w};
#pragma unroll
            for (int i = 0; i < 4; ++i)
#pragma unroll
                for (int j = 0; j < 4; ++j)
                    acc[i][j] = fmaf(a[i], b[j], acc[i][j]);
        }
        __syncthreads();
    }

#pragma unroll
    for (int i = 0; i < 4; ++i) {
        const int row = m0 + ty * 4 + i;
#pragma unroll
        for (int j = 0; j < 4; ++j) {
            const int col = n0 + tx * 4 + j;
            float v = acc[i][j] * alpha;
            if (bias)  v += bias[col];
            if (resid) v += resid[(long)row * ldc + col];
            if (pos)   v += pos[(long)(row & (SEQ - 1)) * D_MODEL + col];
            C[(long)row * ldc + col] = v;
        }
    }
}

// ---------------------------------------------------------------------------
// LayerNorm over D_MODEL=512; one block (128 threads, float4/thread) per row.
// Two-pass (mean, then var of centered values) to match reference numerics.
// ---------------------------------------------------------------------------
__global__ void __launch_bounds__(128)
ln_kernel(const float* __restrict__ x, const float* __restrict__ g,
          const float* __restrict__ b, float* __restrict__ o)
{
    __shared__ float sh[4];
    const long row = blockIdx.x;
    const int  t   = threadIdx.x;
    float4 v = ((const float4*)(x + row * D_MODEL))[t];

    float s = v.x + v.y + v.z + v.w;
#pragma unroll
    for (int off = 16; off; off >>= 1) s += __shfl_xor_sync(~0u, s, off);
    if ((t & 31) == 0) sh[t >> 5] = s;
    __syncthreads();
    const float mu = (sh[0] + sh[1] + sh[2] + sh[3]) * (1.f / D_MODEL);

    const float dx = v.x - mu, dy = v.y - mu, dz = v.z - mu, dw = v.w - mu;
    float s2 = dx * dx + dy * dy + dz * dz + dw * dw;
#pragma unroll
    for (int off = 16; off; off >>= 1) s2 += __shfl_xor_sync(~0u, s2, off);
    __syncthreads();
    if ((t & 31) == 0) sh[t >> 5] = s2;
    __syncthreads();
    const float var = (sh[0] + sh[1] + sh[2] + sh[3]) * (1.f / D_MODEL);
    const float r   = rsqrtf(var + 1e-5f);

    float4 gg = ((const float4*)g)[t];
    float4 bb = ((const float4*)b)[t];
    float4 ov;
    ov.x = dx * r * gg.x + bb.x;
    ov.y = dy * r * gg.y + bb.y;
    ov.z = dz * r * gg.z + bb.z;
    ov.w = dw * r * gg.w + bb.w;
    ((float4*)(o + row * D_MODEL))[t] = ov;
}

// ---------------------------------------------------------------------------
// Sparsemax over rows of length SEQ=1024, in place. One block (256 thr) / row.
// Solves sum(max(z - tau, 0)) = 1 by 32-step bisection on tau in
// [zmax-1, zmax] (exact sparsemax threshold; converges to ~2^-32).
// ---------------------------------------------------------------------------
__global__ void __launch_bounds__(256)
sparsemax_kernel(float* __restrict__ sim)
{
    __shared__ float sh[8];
    const long row = blockIdx.x;
    const int  t   = threadIdx.x;
    float4 z = ((const float4*)(sim + row * (long)SEQ))[t];

    float m = fmaxf(fmaxf(z.x, z.y), fmaxf(z.z, z.w));
#pragma unroll
    for (int off = 16; off; off >>= 1) m = fmaxf(m, __shfl_xor_sync(~0u, m, off));
    if ((t & 31) == 0) sh[t >> 5] = m;
    __syncthreads();
    float zmax = sh[0];
#pragma unroll
    for (int w = 1; w < 8; ++w) zmax = fmaxf(zmax, sh[w]);

    float lo = zmax - 1.f, hi = zmax;
#pragma unroll 1
    for (int it = 0; it < 32; ++it) {
        const float tau = 0.5f * (lo + hi);
        float s = fmaxf(z.x - tau, 0.f) + fmaxf(z.y - tau, 0.f)
                + fmaxf(z.z - tau, 0.f) + fmaxf(z.w - tau, 0.f);
#pragma unroll
        for (int off = 16; off; off >>= 1) s += __shfl_xor_sync(~0u, s, off);
        __syncthreads();
        if ((t & 31) == 0) sh[t >> 5] = s;
        __syncthreads();
        const float tot = sh[0] + sh[1] + sh[2] + sh[3]
                        + sh[4] + sh[5] + sh[6] + sh[7];
        if (tot >= 1.f) lo = tau; else hi = tau;   // identical on all threads
    }
    const float tau = 0.5f * (lo + hi);
    float4 o;
    o.x = fmaxf(z.x - tau, 0.f);
    o.y = fmaxf(z.y - tau, 0.f);
    o.z = fmaxf(z.z - tau, 0.f);
    o.w = fmaxf(z.w - tau, 0.f);
    ((float4*)(sim + row * (long)SEQ))[t] = o;
}

// ---------------------------------------------------------------------------
// GEGLU: o[row, j] = hh[row, j] * gelu_exact(hh[row, j + FF]),  hh rows of 2*FF
// ---------------------------------------------------------------------------
__global__ void __launch_bounds__(256)
geglu_kernel(const float* __restrict__ hh, float* __restrict__ o)
{
    const long i   = (long)blockIdx.x * blockDim.x + threadIdx.x;  // < NROWS*FF
    const long row = i >> 11;            // FF = 2048
    const int  col = (int)(i & (FF - 1));
    const float a = hh[row * (2 * FF) + col];
    const float g = hh[row * (2 * FF) + FF + col];
    o[i] = a * g * normcdff(g);          // exact gelu: g * Phi(g)
}

// ---------------------------------------------------------------------------
// Mean pool over sequence: out[b, d] = mean_s x[b, s, d].  Two deterministic
// stages (no atomics): 8 chunk partials per (b,d), then combine.
// ---------------------------------------------------------------------------
__global__ void __launch_bounds__(512)
pool1_kernel(const float* __restrict__ x, float* __restrict__ p)
{
    const int b = blockIdx.x, c = blockIdx.y;   // 8 x 8
    const int d = threadIdx.x;                  // 512
    float s = 0.f;
    const float* base = x + ((long)b * SEQ + c * 128) * D_MODEL + d;
    for (int i = 0; i < 128; ++i) s += base[(long)i * D_MODEL];
    p[(b * 8 + c) * D_MODEL + d] = s;
}

__global__ void __launch_bounds__(256)
pool2_kernel(const float* __restrict__ p, float* __restrict__ o)
{
    const int i = blockIdx.x * blockDim.x + threadIdx.x;  // 4096
    const int b = i >> 9, d = i & 511;
    float s = 0.f;
#pragma unroll
    for (int c = 0; c < 8; ++c) s += p[(b * 8 + c) * D_MODEL + d];
    o[i] = s * (1.f / SEQ);
}

// ---------------------------------------------------------------------------
static void launch_gemm(bool transB,
                        const float* A, int lda, long aO, long aI,
                        const float* B, int ldb, long bO, long bI,
                        float* C, int ldc, long cO, long cI,
                        int M, int N, int K, int batches,
                        const float* bias, const float* resid,
                        const float* pos, float alpha)
{
    dim3 grid(N / 64, M / 64, batches);
    if (transB)
        gemm_kernel<true><<<grid, 256>>>(A, lda, aO, aI, B, ldb, bO, bI,
                                         C, ldc, cO, cI, K, bias, resid, pos, alpha);
    else
        gemm_kernel<false><<<grid, 256>>>(A, lda, aO, aI, B, ldb, bO, bI,
                                          C, ldc, cO, cI, K, bias, resid, pos, alpha);
}

extern "C" void kernel_launch(void* const* d_in, const int* in_sizes, int n_in,
                              void* d_out, int out_size)
{
    const float* x      = (const float*)d_in[0];
    const float* proj_w = (const float*)d_in[1];
    const float* proj_b = (const float*)d_in[2];
    const float* pos    = (const float*)d_in[3];
    const float* ln1_g  = (const float*)d_in[4];
    const float* ln1_b  = (const float*)d_in[5];
    const float* wqkv   = (const float*)d_in[6];
    const float* wout   = (const float*)d_in[7];
    const float* bout   = (const float*)d_in[8];
    const float* ln2_g  = (const float*)d_in[9];
    const float* ln2_b  = (const float*)d_in[10];
    const float* w1     = (const float*)d_in[11];
    const float* b1     = (const float*)d_in[12];
    const float* w2     = (const float*)d_in[13];
    const float* b2     = (const float*)d_in[14];
    float* out = (float*)d_out;

    float *gx, *gh, *gqkv, *gsim, *gao, *ghh, *gffg, *gpool;
    cudaGetSymbolAddress((void**)&gx,    g_x);
    cudaGetSymbolAddress((void**)&gh,    g_h);
    cudaGetSymbolAddress((void**)&gqkv,  g_qkv);
    cudaGetSymbolAddress((void**)&gsim,  g_sim);
    cudaGetSymbolAddress((void**)&gao,   g_ao);
    cudaGetSymbolAddress((void**)&ghh,   g_hh);
    cudaGetSymbolAddress((void**)&gffg,  g_ffg);
    cudaGetSymbolAddress((void**)&gpool, g_pool);

    // x = x @ proj_w + proj_b + pos_emb[:S]
    launch_gemm(false, x, D_MODEL, 0, 0, proj_w, D_MODEL, 0, 0,
                gx, D_MODEL, 0, 0, NROWS, D_MODEL, D_MODEL, 1,
                proj_b, nullptr, pos, 1.f);

    const float scale = 0.125f;  // DIM_HEAD^-0.5

    for (int l = 0; l < NDEPTH; ++l) {
        // --- attention ---
        ln_kernel<<<NROWS, 128>>>(gx, ln1_g + l * D_MODEL, ln1_b + l * D_MODEL, gh);

        launch_gemm(false, gh, D_MODEL, 0, 0,
                    wqkv + (long)l * D_MODEL * (3 * D_MODEL), 3 * D_MODEL, 0, 0,
                    gqkv, 3 * D_MODEL, 0, 0,
                    NROWS, 3 * D_MODEL, D_MODEL, 1, nullptr, nullptr, nullptr, 1.f);

        // sim[b,h] = q[b,h] @ k[b,h]^T * scale   (64 batches: z = b*8 + h)
        launch_gemm(true,
                    gqkv,       3 * D_MODEL, (long)SEQ * 3 * D_MODEL, DHEAD,
                    gqkv + 512, 3 * D_MODEL, (long)SEQ * 3 * D_MODEL, DHEAD,
                    gsim, SEQ, (long)8 * SEQ * SEQ, (long)SEQ * SEQ,
                    SEQ, SEQ, DHEAD, NB * NHEADS,
                    nullptr, nullptr, nullptr, scale);

        sparsemax_kernel<<<NB * NHEADS * SEQ, 256>>>(gsim);

        // ao[b,:,h*64+d] = attn[b,h] @ v[b,h]
        launch_gemm(false,
                    gsim, SEQ, (long)8 * SEQ * SEQ, (long)SEQ * SEQ,
                    gqkv + 1024, 3 * D_MODEL, (long)SEQ * 3 * D_MODEL, DHEAD,
                    gao, D_MODEL, (long)SEQ * D_MODEL, DHEAD,
                    SEQ, DHEAD, SEQ, NB * NHEADS,
                    nullptr, nullptr, nullptr, 1.f);

        // x = x + ao @ wout + bout
        launch_gemm(false, gao, D_MODEL, 0, 0,
                    wout + (long)l * D_MODEL * D_MODEL, D_MODEL, 0, 0,
                    gx, D_MODEL, 0, 0, NROWS, D_MODEL, D_MODEL, 1,
                    bout + l * D_MODEL, gx, nullptr, 1.f);

        // --- GEGLU FFN ---
        ln_kernel<<<NROWS, 128>>>(gx, ln2_g + l * D_MODEL, ln2_b + l * D_MODEL, gh);

        launch_gemm(false, gh, D_MODEL, 0, 0,
                    w1 + (long)l * D_MODEL * (2 * FF), 2 * FF, 0, 0,
                    ghh, 2 * FF, 0, 0, NROWS, 2 * FF, D_MODEL, 1,
                    b1 + (long)l * 2 * FF, nullptr, nullptr, 1.f);

        geglu_kernel<<<(NROWS * FF) / 256, 256>>>(ghh, gffg);

        // x = x + ffg @ w2 + b2
        launch_gemm(false, gffg, FF, 0, 0,
                    w2 + (long)l * FF * D_MODEL, D_MODEL, 0, 0,
                    gx, D_MODEL, 0, 0, NROWS, D_MODEL, FF, 1,
                    b2 + l * D_MODEL, gx, nullptr, 1.f);
    }

    pool1_kernel<<<dim3(NB, 8), 512>>>(gx, gpool);
    pool2_kernel<<<16, 256>>>(gpool, out);
}

// round 4
// speedup vs baseline: 1.3475x; 1.3475x over previous
#include <cuda_runtime.h>
#include <cmath>
#include <cstdint>

#define D_MODEL 512
#define SEQ     1024
#define NB      8
#define NHEADS  8
#define DHEAD   64
#define FF      2048
#define NROWS   (NB*SEQ)    /* 8192 */
#define NDEPTH  3

// ---------------- scratch (device globals; no allocation allowed) ----------
__device__ float g_x   [NROWS * D_MODEL];
__device__ float g_h   [NROWS * D_MODEL];
__device__ float g_qkv [NROWS * 3 * D_MODEL];
__device__ float g_sim [67108864];                 // 64 * 1024 * 1024
__device__ float g_ao  [NROWS * D_MODEL];
__device__ float g_hh  [NROWS * 2 * FF];
__device__ float g_ffg [NROWS * FF];
__device__ float g_pool[NB * 8 * D_MODEL];
__device__ float g_wt  [12845056];                 // transposed weights
__device__ float g_vt  [NB * NHEADS * DHEAD * SEQ];// V^T per (b,h): [64][1024]

#define OFF_PROJ 0
#define OFF_QKV  262144
#define OFF_WOUT 2621440
#define OFF_W1   3407872
#define OFF_W2   9699328

// ---------------------------------------------------------------------------
__device__ __forceinline__ void cp16(uint32_t sa, const float* ga) {
    asm volatile("cp.async.cg.shared.global [%0], [%1], 16;" :: "r"(sa), "l"(ga) : "memory");
}
__device__ __forceinline__ uint32_t smem_u32(const void* p) {
    uint32_t a;
    asm("{ .reg .u64 t; cvta.to.shared.u64 t, %1; cvt.u32.u64 %0, t; }"
        : "=r"(a) : "l"(p));
    return a;
}
__device__ __forceinline__ void cp_commit() {
    asm volatile("cp.async.commit_group;" ::: "memory");
}
__device__ __forceinline__ void cp_wait_n(int n) {
    if (n >= 2)      asm volatile("cp.async.wait_group 2;" ::: "memory");
    else if (n == 1) asm volatile("cp.async.wait_group 1;" ::: "memory");
    else             asm volatile("cp.async.wait_group 0;" ::: "memory");
}
__device__ __forceinline__ void mma8(float* d, const uint32_t* a, const uint32_t* b) {
    asm volatile(
        "mma.sync.aligned.m16n8k8.row.col.f32.tf32.tf32.f32 "
        "{%0,%1,%2,%3}, {%4,%5,%6,%7}, {%8,%9}, {%0,%1,%2,%3};"
        : "+f"(d[0]), "+f"(d[1]), "+f"(d[2]), "+f"(d[3])
        : "r"(a[0]), "r"(a[1]), "r"(a[2]), "r"(a[3]), "r"(b[0]), "r"(b[1]));
}
// tf32x3 split: x = hi + lo (both tf32-representable); dropped term ~2^-22 rel
__device__ __forceinline__ void split1(float x, uint32_t& hi, uint32_t& lo) {
    asm("cvt.rna.tf32.f32 %0, %1;" : "=r"(hi) : "f"(x));
    const float r = x - __uint_as_float(hi);
    asm("cvt.rna.tf32.f32 %0, %1;" : "=r"(lo) : "f"(r));
}

// ---------------------------------------------------------------------------
// tf32x3 mma.sync GEMM:  C[M,N] = alpha * A[M,K] @ Bt[N,K]^T (+bias+resid+pos)
// A row-major [M,K], Bt row-major [N,K]. M%128==0, N%BN==0, K%32==0.
// Batched via blockIdx.z -> (zo=z>>3, zi=z&7).
// smem rows padded to 144B -> fragment loads conflict-free.
// ---------------------------------------------------------------------------
template<int BN>
__global__ void __launch_bounds__(256, 2)
mgemm_kernel(const float* __restrict__ A, long lda, long aO, long aI,
             const float* __restrict__ B, long ldb, long bO, long bI,
             float* __restrict__ C, long ldc, long cO, long cI,
             int K,
             const float* __restrict__ bias,
             const float* __restrict__ resid,
             const float* __restrict__ pos,
             float alpha)
{
    constexpr int BM = 128;
    constexpr int WN = BN / 2;       // warp tile: 32 x WN (4x2 warp grid)
    constexpr int NI = WN / 8;       // n-tiles per warp
    constexpr int PITCH = 36;        // floats per smem row (144B)
    constexpr int STAGE_F = (BM + BN) * PITCH;

    extern __shared__ float smem[];

    const int z = blockIdx.z, zo = z >> 3, zi = z & 7;
    A += zo * aO + zi * aI;
    B += zo * bO + zi * bI;
    C += zo * cO + zi * cI;
    const float* Rz = resid ? resid + zo * cO + zi * cI : nullptr;

    const long m0 = (long)blockIdx.y * BM;
    const long n0 = (long)blockIdx.x * BN;
    A += m0 * lda;
    B += n0 * ldb;

    const int t    = threadIdx.x;
    const int wid  = t >> 5, lane = t & 31;
    const int wr   = wid & 3, wc = wid >> 2;
    const int g    = lane >> 2, c = lane & 3;

    const uint32_t sbase = smem_u32(smem);
    const int niter = K >> 5;

    auto load_stage = [&](int s, int kc) {
        const uint32_t sA = sbase + (uint32_t)(s * STAGE_F) * 4u;
        const uint32_t sB = sA + BM * PITCH * 4u;
        const float* ga = A + kc * 32;
        const float* gb = B + kc * 32;
        const int r0  = t >> 3;
        const int seg = (t & 7) * 16;
#pragma unroll
        for (int p = 0; p < BM / 32; ++p) {
            const int r = p * 32 + r0;
            cp16(sA + r * 144 + seg, ga + (long)r * lda + (t & 7) * 4);
        }
#pragma unroll
        for (int p = 0; p < BN / 32; ++p) {
            const int r = p * 32 + r0;
            cp16(sB + r * 144 + seg, gb + (long)r * ldb + (t & 7) * 4);
        }
        cp_commit();
    };

    float acc[2][NI][4];
#pragma unroll
    for (int mi = 0; mi < 2; ++mi)
#pragma unroll
        for (int ni = 0; ni < NI; ++ni)
#pragma unroll
            for (int j = 0; j < 4; ++j) acc[mi][ni][j] = 0.f;

    const int pre = niter < 3 ? niter : 3;
    for (int p = 0; p < pre; ++p) load_stage(p, p);

    for (int i = 0; i < niter; ++i) {
        const int s = i % 3;
        const int issued = (i + 3 < niter) ? i + 3 : niter;
        cp_wait_n(issued - i - 1);
        __syncthreads();

        const float* As = smem + s * STAGE_F;
        const float* Bs = As + BM * PITCH;

#pragma unroll
        for (int kk = 0; kk < 32; kk += 8) {
            uint32_t afh[2][4], afl[2][4];
#pragma unroll
            for (int mi = 0; mi < 2; ++mi) {
                const int rb = (wr * 32 + mi * 16 + g) * PITCH + kk + c;
                split1(As[rb],                 afh[mi][0], afl[mi][0]);
                split1(As[rb + 8 * PITCH],     afh[mi][1], afl[mi][1]);
                split1(As[rb + 4],             afh[mi][2], afl[mi][2]);
                split1(As[rb + 8 * PITCH + 4], afh[mi][3], afl[mi][3]);
            }
            uint32_t bfh[NI][2], bfl[NI][2];
#pragma unroll
            for (int ni = 0; ni < NI; ++ni) {
                const int rb = (wc * WN + ni * 8 + g) * PITCH + kk + c;
                split1(Bs[rb],     bfh[ni][0], bfl[ni][0]);
                split1(Bs[rb + 4], bfh[ni][1], bfl[ni][1]);
            }
#pragma unroll
            for (int mi = 0; mi < 2; ++mi)
#pragma unroll
                for (int ni = 0; ni < NI; ++ni) {
                    mma8(acc[mi][ni], afl[mi], bfh[ni]);
                    mma8(acc[mi][ni], afh[mi], bfl[ni]);
                    mma8(acc[mi][ni], afh[mi], bfh[ni]);
                }
        }

        if (i + 3 < niter) {
            __syncthreads();
            load_stage(s, i + 3);
        }
    }

    // ---- epilogue: direct fragment stores (float2) ----
#pragma unroll
    for (int mi = 0; mi < 2; ++mi) {
#pragma unroll
        for (int ni = 0; ni < NI; ++ni) {
            const long col = n0 + wc * WN + ni * 8 + 2 * c;
#pragma unroll
            for (int h = 0; h < 2; ++h) {
                const long row = m0 + wr * 32 + mi * 16 + g + h * 8;
                float vx = acc[mi][ni][2 * h]     * alpha;
                float vy = acc[mi][ni][2 * h + 1] * alpha;
                if (bias) {
                    float2 bv = *(const float2*)&bias[col];
                    vx += bv.x; vy += bv.y;
                }
                const long off = row * ldc + col;
                if (Rz) {
                    float2 rv = *(const float2*)&Rz[off];
                    vx += rv.x; vy += rv.y;
                }
                if (pos) {
                    float2 pv = *(const float2*)&pos[(row & (SEQ - 1)) * D_MODEL + col];
                    vx += pv.x; vy += pv.y;
                }
                *(float2*)&C[off] = make_float2(vx, vy);
            }
        }
    }
}

// ---------------------------------------------------------------------------
__global__ void __launch_bounds__(256)
transpose_kernel(const float* __restrict__ in, long ldi, long iO, long iI,
                 float* __restrict__ out, long ldo, long oO, long oI)
{
    __shared__ float tile[32][33];
    const int z = blockIdx.z;
    in  += (z >> 3) * iO + (z & 7) * iI;
    out += (z >> 3) * oO + (z & 7) * oI;
    const long r0 = (long)blockIdx.y * 32, c0 = (long)blockIdx.x * 32;
#pragma unroll
    for (int i = 0; i < 32; i += 8)
        tile[threadIdx.y + i][threadIdx.x] =
            in[(r0 + threadIdx.y + i) * ldi + c0 + threadIdx.x];
    __syncthreads();
#pragma unroll
    for (int i = 0; i < 32; i += 8)
        out[(c0 + threadIdx.y + i) * ldo + r0 + threadIdx.x] =
            tile[threadIdx.x][threadIdx.y + i];
}

// ---------------------------------------------------------------------------
__global__ void __launch_bounds__(128)
ln_kernel(const float* __restrict__ x, const float* __restrict__ g,
          const float* __restrict__ b, float* __restrict__ o)
{
    __shared__ float sh[4];
    const long row = blockIdx.x;
    const int  t   = threadIdx.x;
    float4 v = ((const float4*)(x + row * D_MODEL))[t];

    float s = v.x + v.y + v.z + v.w;
#pragma unroll
    for (int off = 16; off; off >>= 1) s += __shfl_xor_sync(~0u, s, off);
    if ((t & 31) == 0) sh[t >> 5] = s;
    __syncthreads();
    const float mu = (sh[0] + sh[1] + sh[2] + sh[3]) * (1.f / D_MODEL);

    const float dx = v.x - mu, dy = v.y - mu, dz = v.z - mu, dw = v.w - mu;
    float s2 = dx * dx + dy * dy + dz * dz + dw * dw;
#pragma unroll
    for (int off = 16; off; off >>= 1) s2 += __shfl_xor_sync(~0u, s2, off);
    __syncthreads();
    if ((t & 31) == 0) sh[t >> 5] = s2;
    __syncthreads();
    const float var = (sh[0] + sh[1] + sh[2] + sh[3]) * (1.f / D_MODEL);
    const float r   = rsqrtf(var + 1e-5f);

    float4 gg = ((const float4*)g)[t];
    float4 bb = ((const float4*)b)[t];
    float4 ov;
    ov.x = dx * r * gg.x + bb.x;
    ov.y = dy * r * gg.y + bb.y;
    ov.z = dz * r * gg.z + bb.z;
    ov.w = dw * r * gg.w + bb.w;
    ((float4*)(o + row * D_MODEL))[t] = ov;
}

// ---------------------------------------------------------------------------
__global__ void __launch_bounds__(256)
sparsemax_kernel(float* __restrict__ sim)
{
    __shared__ float sh[8];
    const long row = blockIdx.x;
    const int  t   = threadIdx.x;
    float4 z = ((const float4*)(sim + row * (long)SEQ))[t];

    float m = fmaxf(fmaxf(z.x, z.y), fmaxf(z.z, z.w));
#pragma unroll
    for (int off = 16; off; off >>= 1) m = fmaxf(m, __shfl_xor_sync(~0u, m, off));
    if ((t & 31) == 0) sh[t >> 5] = m;
    __syncthreads();
    float zmax = sh[0];
#pragma unroll
    for (int w = 1; w < 8; ++w) zmax = fmaxf(zmax, sh[w]);

    float lo = zmax - 1.f, hi = zmax;
#pragma unroll 1
    for (int it = 0; it < 32; ++it) {
        const float tau = 0.5f * (lo + hi);
        float s = fmaxf(z.x - tau, 0.f) + fmaxf(z.y - tau, 0.f)
                + fmaxf(z.z - tau, 0.f) + fmaxf(z.w - tau, 0.f);
#pragma unroll
        for (int off = 16; off; off >>= 1) s += __shfl_xor_sync(~0u, s, off);
        __syncthreads();
        if ((t & 31) == 0) sh[t >> 5] = s;
        __syncthreads();
        const float tot = sh[0] + sh[1] + sh[2] + sh[3]
                        + sh[4] + sh[5] + sh[6] + sh[7];
        if (tot >= 1.f) lo = tau; else hi = tau;
    }
    const float tau = 0.5f * (lo + hi);
    float4 o;
    o.x = fmaxf(z.x - tau, 0.f);
    o.y = fmaxf(z.y - tau, 0.f);
    o.z = fmaxf(z.z - tau, 0.f);
    o.w = fmaxf(z.w - tau, 0.f);
    ((float4*)(sim + row * (long)SEQ))[t] = o;
}

// ---------------------------------------------------------------------------
__global__ void __launch_bounds__(256)
geglu_kernel(const float* __restrict__ hh, float* __restrict__ o)
{
    const long i   = (long)blockIdx.x * blockDim.x + threadIdx.x;
    const long row = i >> 11;
    const int  col = (int)(i & (FF - 1));
    const float a = hh[row * (2 * FF) + col];
    const float g = hh[row * (2 * FF) + FF + col];
    o[i] = a * g * normcdff(g);
}

__global__ void __launch_bounds__(512)
pool1_kernel(const float* __restrict__ x, float* __restrict__ p)
{
    const int b = blockIdx.x, cc = blockIdx.y;
    const int d = threadIdx.x;
    float s = 0.f;
    const float* base = x + ((long)b * SEQ + cc * 128) * D_MODEL + d;
    for (int i = 0; i < 128; ++i) s += base[(long)i * D_MODEL];
    p[(b * 8 + cc) * D_MODEL + d] = s;
}

__global__ void __launch_bounds__(256)
pool2_kernel(const float* __restrict__ p, float* __restrict__ o)
{
    const int i = blockIdx.x * blockDim.x + threadIdx.x;
    const int b = i >> 9, d = i & 511;
    float s = 0.f;
#pragma unroll
    for (int cc = 0; cc < 8; ++cc) s += p[(b * 8 + cc) * D_MODEL + d];
    o[i] = s * (1.f / SEQ);
}

// ---------------------------------------------------------------------------
#define SMEM_BN128 (3 * (128 + 128) * 144)
#define SMEM_BN64  (3 * (128 +  64) * 144)

template<int BN>
static void launch_mg(const float* A, long lda, long aO, long aI,
                      const float* B, long ldb, long bO, long bI,
                      float* C, long ldc, long cO, long cI,
                      int M, int N, int K, int batches,
                      const float* bias, const float* resid,
                      const float* pos, float alpha)
{
    dim3 grid(N / BN, M / 128, batches);
    const int smem = (BN == 128) ? SMEM_BN128 : SMEM_BN64;
    mgemm_kernel<BN><<<grid, 256, smem>>>(A, lda, aO, aI, B, ldb, bO, bI,
                                          C, ldc, cO, cI, K, bias, resid, pos, alpha);
}

extern "C" void kernel_launch(void* const* d_in, const int* in_sizes, int n_in,
                              void* d_out, int out_size)
{
    const float* x      = (const float*)d_in[0];
    const float* proj_w = (const float*)d_in[1];
    const float* proj_b = (const float*)d_in[2];
    const float* pos    = (const float*)d_in[3];
    const float* ln1_g  = (const float*)d_in[4];
    const float* ln1_b  = (const float*)d_in[5];
    const float* wqkv   = (const float*)d_in[6];
    const float* wout   = (const float*)d_in[7];
    const float* bout   = (const float*)d_in[8];
    const float* ln2_g  = (const float*)d_in[9];
    const float* ln2_b  = (const float*)d_in[10];
    const float* w1     = (const float*)d_in[11];
    const float* b1     = (const float*)d_in[12];
    const float* w2     = (const float*)d_in[13];
    const float* b2     = (const float*)d_in[14];
    float* out = (float*)d_out;

    cudaFuncSetAttribute(mgemm_kernel<128>,
                         cudaFuncAttributeMaxDynamicSharedMemorySize, SMEM_BN128);
    cudaFuncSetAttribute(mgemm_kernel<64>,
                         cudaFuncAttributeMaxDynamicSharedMemorySize, SMEM_BN64);

    float *gx, *gh, *gqkv, *gsim, *gao, *ghh, *gffg, *gpool, *gwt, *gvt;
    cudaGetSymbolAddress((void**)&gx,    g_x);
    cudaGetSymbolAddress((void**)&gh,    g_h);
    cudaGetSymbolAddress((void**)&gqkv,  g_qkv);
    cudaGetSymbolAddress((void**)&gsim,  g_sim);
    cudaGetSymbolAddress((void**)&gao,   g_ao);
    cudaGetSymbolAddress((void**)&ghh,   g_hh);
    cudaGetSymbolAddress((void**)&gffg,  g_ffg);
    cudaGetSymbolAddress((void**)&gpool, g_pool);
    cudaGetSymbolAddress((void**)&gwt,   g_wt);
    cudaGetSymbolAddress((void**)&gvt,   g_vt);

    // ---- weight transposes (B operands as [N,K] row-major) ----
    transpose_kernel<<<dim3(16, 16, 1), dim3(32, 8)>>>(
        proj_w, D_MODEL, 0, 0, gwt + OFF_PROJ, D_MODEL, 0, 0);
    transpose_kernel<<<dim3(48, 16, 3), dim3(32, 8)>>>(
        wqkv, 3 * D_MODEL, 0, (long)D_MODEL * 3 * D_MODEL,
        gwt + OFF_QKV, D_MODEL, 0, (long)3 * D_MODEL * D_MODEL);
    transpose_kernel<<<dim3(16, 16, 3), dim3(32, 8)>>>(
        wout, D_MODEL, 0, (long)D_MODEL * D_MODEL,
        gwt + OFF_WOUT, D_MODEL, 0, (long)D_MODEL * D_MODEL);
    transpose_kernel<<<dim3(128, 16, 3), dim3(32, 8)>>>(
        w1, 2 * FF, 0, (long)D_MODEL * 2 * FF,
        gwt + OFF_W1, D_MODEL, 0, (long)2 * FF * D_MODEL);
    transpose_kernel<<<dim3(16, 64, 3), dim3(32, 8)>>>(
        w2, D_MODEL, 0, (long)FF * D_MODEL,
        gwt + OFF_W2, FF, 0, (long)D_MODEL * FF);

    // x = x @ proj_w + proj_b + pos
    launch_mg<128>(x, D_MODEL, 0, 0, gwt + OFF_PROJ, D_MODEL, 0, 0,
                   gx, D_MODEL, 0, 0, NROWS, D_MODEL, D_MODEL, 1,
                   proj_b, nullptr, pos, 1.f);

    const float scale = 0.125f;

    for (int l = 0; l < NDEPTH; ++l) {
        ln_kernel<<<NROWS, 128>>>(gx, ln1_g + l * D_MODEL, ln1_b + l * D_MODEL, gh);

        // qkv = h @ Wqkv
        launch_mg<128>(gh, D_MODEL, 0, 0,
                       gwt + OFF_QKV + (long)l * 3 * D_MODEL * D_MODEL, D_MODEL, 0, 0,
                       gqkv, 3 * D_MODEL, 0, 0,
                       NROWS, 3 * D_MODEL, D_MODEL, 1, nullptr, nullptr, nullptr, 1.f);

        // V^T per (b,h): [1024,64] -> [64,1024]
        transpose_kernel<<<dim3(2, 32, NB * NHEADS), dim3(32, 8)>>>(
            gqkv + 2 * D_MODEL, 3 * D_MODEL, (long)SEQ * 3 * D_MODEL, DHEAD,
            gvt, SEQ, (long)NHEADS * DHEAD * SEQ, (long)DHEAD * SEQ);

        // sim = q @ k^T * scale
        launch_mg<128>(gqkv,           3 * D_MODEL, (long)SEQ * 3 * D_MODEL, DHEAD,
                       gqkv + D_MODEL, 3 * D_MODEL, (long)SEQ * 3 * D_MODEL, DHEAD,
                       gsim, SEQ, (long)NHEADS * SEQ * SEQ, (long)SEQ * SEQ,
                       SEQ, SEQ, DHEAD, NB * NHEADS,
                       nullptr, nullptr, nullptr, scale);

        sparsemax_kernel<<<NB * NHEADS * SEQ, 256>>>(gsim);

        // ao = attn @ v
        launch_mg<64>(gsim, SEQ, (long)NHEADS * SEQ * SEQ, (long)SEQ * SEQ,
                      gvt,  SEQ, (long)NHEADS * DHEAD * SEQ, (long)DHEAD * SEQ,
                      gao, D_MODEL, (long)SEQ * D_MODEL, DHEAD,
                      SEQ, DHEAD, SEQ, NB * NHEADS,
                      nullptr, nullptr, nullptr, 1.f);

        // x = x + ao @ Wout + bout
        launch_mg<128>(gao, D_MODEL, 0, 0,
                       gwt + OFF_WOUT + (long)l * D_MODEL * D_MODEL, D_MODEL, 0, 0,
                       gx, D_MODEL, 0, 0, NROWS, D_MODEL, D_MODEL, 1,
                       bout + l * D_MODEL, gx, nullptr, 1.f);

        ln_kernel<<<NROWS, 128>>>(gx, ln2_g + l * D_MODEL, ln2_b + l * D_MODEL, gh);

        // hh = h @ W1 + b1
        launch_mg<128>(gh, D_MODEL, 0, 0,
                       gwt + OFF_W1 + (long)l * 2 * FF * D_MODEL, D_MODEL, 0, 0,
                       ghh, 2 * FF, 0, 0, NROWS, 2 * FF, D_MODEL, 1,
                       b1 + (long)l * 2 * FF, nullptr, nullptr, 1.f);

        geglu_kernel<<<(NROWS * FF) / 256, 256>>>(ghh, gffg);

        // x = x + ffg @ W2 + b2
        launch_mg<128>(gffg, FF, 0, 0,
                       gwt + OFF_W2 + (long)l * D_MODEL * FF, FF, 0, 0,
                       gx, D_MODEL, 0, 0, NROWS, D_MODEL, FF, 1,
                       b2 + l * D_MODEL, gx, nullptr, 1.f);
    }

    pool1_kernel<<<dim3(NB, 8), 512>>>(gx, gpool);
    pool2_kernel<<<16, 256>>>(gpool, out);
}

// round 5
// speedup vs baseline: 1.7397x; 1.2911x over previous
#include <cuda_runtime.h>
#include <cmath>
#include <cstdint>

#define D_MODEL 512
#define SEQ     1024
#define NB      8
#define NHEADS  8
#define DHEAD   64
#define FF      2048
#define NROWS   (NB*SEQ)    /* 8192 */
#define NDEPTH  3

// ---------------- scratch (device globals; no allocation allowed) ----------
__device__ float g_x   [NROWS * D_MODEL];
__device__ float g_h   [NROWS * D_MODEL];
__device__ float g_qkv [NROWS * 3 * D_MODEL];
__device__ float g_sim [67108864];                 // 64 * 1024 * 1024
__device__ float g_ao  [NROWS * D_MODEL];
__device__ float g_hh  [NROWS * 2 * FF];
__device__ float g_ffg [NROWS * FF];
__device__ float g_pool[NB * 8 * D_MODEL];
__device__ float g_wt  [12845056];                 // transposed weights
__device__ float g_vt  [NB * NHEADS * DHEAD * SEQ];// V^T per (b,h): [64][1024]

#define OFF_PROJ 0
#define OFF_QKV  262144
#define OFF_WOUT 2621440
#define OFF_W1   3407872
#define OFF_W2   9699328

// ---------------------------------------------------------------------------
__device__ __forceinline__ void cp16(uint32_t sa, const float* ga) {
    asm volatile("cp.async.cg.shared.global [%0], [%1], 16;" :: "r"(sa), "l"(ga) : "memory");
}
__device__ __forceinline__ uint32_t smem_u32(const void* p) {
    uint32_t a;
    asm("{ .reg .u64 t; cvta.to.shared.u64 t, %1; cvt.u32.u64 %0, t; }"
        : "=r"(a) : "l"(p));
    return a;
}
__device__ __forceinline__ void cp_commit() {
    asm volatile("cp.async.commit_group;" ::: "memory");
}
__device__ __forceinline__ void cp_wait_n(int n) {
    if (n >= 2)      asm volatile("cp.async.wait_group 2;" ::: "memory");
    else if (n == 1) asm volatile("cp.async.wait_group 1;" ::: "memory");
    else             asm volatile("cp.async.wait_group 0;" ::: "memory");
}
__device__ __forceinline__ void mma8(float* d, const uint32_t* a, const uint32_t* b) {
    asm volatile(
        "mma.sync.aligned.m16n8k8.row.col.f32.tf32.tf32.f32 "
        "{%0,%1,%2,%3}, {%4,%5,%6,%7}, {%8,%9}, {%0,%1,%2,%3};"
        : "+f"(d[0]), "+f"(d[1]), "+f"(d[2]), "+f"(d[3])
        : "r"(a[0]), "r"(a[1]), "r"(a[2]), "r"(a[3]), "r"(b[0]), "r"(b[1]));
}
// tf32x3 split: x = hi + lo (both tf32-representable); dropped term ~2^-22 rel
__device__ __forceinline__ void split1(float x, uint32_t& hi, uint32_t& lo) {
    asm("cvt.rna.tf32.f32 %0, %1;" : "=r"(hi) : "f"(x));
    const float r = x - __uint_as_float(hi);
    asm("cvt.rna.tf32.f32 %0, %1;" : "=r"(lo) : "f"(r));
}

// ---------------------------------------------------------------------------
// tf32x3 mma.sync GEMM:  C[M,N] = alpha * A[M,K] @ Bt[N,K]^T (+bias+resid+pos)
// ---------------------------------------------------------------------------
template<int BN>
__global__ void __launch_bounds__(256, 2)
mgemm_kernel(const float* __restrict__ A, long lda, long aO, long aI,
             const float* __restrict__ B, long ldb, long bO, long bI,
             float* __restrict__ C, long ldc, long cO, long cI,
             int K,
             const float* __restrict__ bias,
             const float* __restrict__ resid,
             const float* __restrict__ pos,
             float alpha)
{
    constexpr int BM = 128;
    constexpr int WN = BN / 2;       // warp tile: 32 x WN (4x2 warp grid)
    constexpr int NI = WN / 8;       // n-tiles per warp
    constexpr int PITCH = 36;        // floats per smem row (144B)
    constexpr int STAGE_F = (BM + BN) * PITCH;

    extern __shared__ float smem[];

    const int z = blockIdx.z, zo = z >> 3, zi = z & 7;
    A += zo * aO + zi * aI;
    B += zo * bO + zi * bI;
    C += zo * cO + zi * cI;
    const float* Rz = resid ? resid + zo * cO + zi * cI : nullptr;

    const long m0 = (long)blockIdx.y * BM;
    const long n0 = (long)blockIdx.x * BN;
    A += m0 * lda;
    B += n0 * ldb;

    const int t    = threadIdx.x;
    const int wid  = t >> 5, lane = t & 31;
    const int wr   = wid & 3, wc = wid >> 2;
    const int g    = lane >> 2, c = lane & 3;

    const uint32_t sbase = smem_u32(smem);
    const int niter = K >> 5;

    auto load_stage = [&](int s, int kc) {
        const uint32_t sA = sbase + (uint32_t)(s * STAGE_F) * 4u;
        const uint32_t sB = sA + BM * PITCH * 4u;
        const float* ga = A + kc * 32;
        const float* gb = B + kc * 32;
        const int r0  = t >> 3;
        const int seg = (t & 7) * 16;
#pragma unroll
        for (int p = 0; p < BM / 32; ++p) {
            const int r = p * 32 + r0;
            cp16(sA + r * 144 + seg, ga + (long)r * lda + (t & 7) * 4);
        }
#pragma unroll
        for (int p = 0; p < BN / 32; ++p) {
            const int r = p * 32 + r0;
            cp16(sB + r * 144 + seg, gb + (long)r * ldb + (t & 7) * 4);
        }
        cp_commit();
    };

    float acc[2][NI][4];
#pragma unroll
    for (int mi = 0; mi < 2; ++mi)
#pragma unroll
        for (int ni = 0; ni < NI; ++ni)
#pragma unroll
            for (int j = 0; j < 4; ++j) acc[mi][ni][j] = 0.f;

    const int pre = niter < 3 ? niter : 3;
    for (int p = 0; p < pre; ++p) load_stage(p, p);

    for (int i = 0; i < niter; ++i) {
        const int s = i % 3;
        const int issued = (i + 3 < niter) ? i + 3 : niter;
        cp_wait_n(issued - i - 1);
        __syncthreads();

        const float* As = smem + s * STAGE_F;
        const float* Bs = As + BM * PITCH;

#pragma unroll
        for (int kk = 0; kk < 32; kk += 8) {
            uint32_t afh[2][4], afl[2][4];
#pragma unroll
            for (int mi = 0; mi < 2; ++mi) {
                const int rb = (wr * 32 + mi * 16 + g) * PITCH + kk + c;
                split1(As[rb],                 afh[mi][0], afl[mi][0]);
                split1(As[rb + 8 * PITCH],     afh[mi][1], afl[mi][1]);
                split1(As[rb + 4],             afh[mi][2], afl[mi][2]);
                split1(As[rb + 8 * PITCH + 4], afh[mi][3], afl[mi][3]);
            }
            uint32_t bfh[NI][2], bfl[NI][2];
#pragma unroll
            for (int ni = 0; ni < NI; ++ni) {
                const int rb = (wc * WN + ni * 8 + g) * PITCH + kk + c;
                split1(Bs[rb],     bfh[ni][0], bfl[ni][0]);
                split1(Bs[rb + 4], bfh[ni][1], bfl[ni][1]);
            }
#pragma unroll
            for (int mi = 0; mi < 2; ++mi)
#pragma unroll
                for (int ni = 0; ni < NI; ++ni) {
                    mma8(acc[mi][ni], afl[mi], bfh[ni]);
                    mma8(acc[mi][ni], afh[mi], bfl[ni]);
                    mma8(acc[mi][ni], afh[mi], bfh[ni]);
                }
        }

        if (i + 3 < niter) {
            __syncthreads();
            load_stage(s, i + 3);
        }
    }

    // ---- epilogue: direct fragment stores (float2) ----
#pragma unroll
    for (int mi = 0; mi < 2; ++mi) {
#pragma unroll
        for (int ni = 0; ni < NI; ++ni) {
            const long col = n0 + wc * WN + ni * 8 + 2 * c;
#pragma unroll
            for (int h = 0; h < 2; ++h) {
                const long row = m0 + wr * 32 + mi * 16 + g + h * 8;
                float vx = acc[mi][ni][2 * h]     * alpha;
                float vy = acc[mi][ni][2 * h + 1] * alpha;
                if (bias) {
                    float2 bv = *(const float2*)&bias[col];
                    vx += bv.x; vy += bv.y;
                }
                const long off = row * ldc + col;
                if (Rz) {
                    float2 rv = *(const float2*)&Rz[off];
                    vx += rv.x; vy += rv.y;
                }
                if (pos) {
                    float2 pv = *(const float2*)&pos[(row & (SEQ - 1)) * D_MODEL + col];
                    vx += pv.x; vy += pv.y;
                }
                *(float2*)&C[off] = make_float2(vx, vy);
            }
        }
    }
}

// ---------------------------------------------------------------------------
__global__ void __launch_bounds__(256)
transpose_kernel(const float* __restrict__ in, long ldi, long iO, long iI,
                 float* __restrict__ out, long ldo, long oO, long oI)
{
    __shared__ float tile[32][33];
    const int z = blockIdx.z;
    in  += (z >> 3) * iO + (z & 7) * iI;
    out += (z >> 3) * oO + (z & 7) * oI;
    const long r0 = (long)blockIdx.y * 32, c0 = (long)blockIdx.x * 32;
#pragma unroll
    for (int i = 0; i < 32; i += 8)
        tile[threadIdx.y + i][threadIdx.x] =
            in[(r0 + threadIdx.y + i) * ldi + c0 + threadIdx.x];
    __syncthreads();
#pragma unroll
    for (int i = 0; i < 32; i += 8)
        out[(c0 + threadIdx.y + i) * ldo + r0 + threadIdx.x] =
            tile[threadIdx.x][threadIdx.y + i];
}

// ---------------------------------------------------------------------------
__global__ void __launch_bounds__(128)
ln_kernel(const float* __restrict__ x, const float* __restrict__ g,
          const float* __restrict__ b, float* __restrict__ o)
{
    __shared__ float sh[4];
    const long row = blockIdx.x;
    const int  t   = threadIdx.x;
    float4 v = ((const float4*)(x + row * D_MODEL))[t];

    float s = v.x + v.y + v.z + v.w;
#pragma unroll
    for (int off = 16; off; off >>= 1) s += __shfl_xor_sync(~0u, s, off);
    if ((t & 31) == 0) sh[t >> 5] = s;
    __syncthreads();
    const float mu = (sh[0] + sh[1] + sh[2] + sh[3]) * (1.f / D_MODEL);

    const float dx = v.x - mu, dy = v.y - mu, dz = v.z - mu, dw = v.w - mu;
    float s2 = dx * dx + dy * dy + dz * dz + dw * dw;
#pragma unroll
    for (int off = 16; off; off >>= 1) s2 += __shfl_xor_sync(~0u, s2, off);
    __syncthreads();
    if ((t & 31) == 0) sh[t >> 5] = s2;
    __syncthreads();
    const float var = (sh[0] + sh[1] + sh[2] + sh[3]) * (1.f / D_MODEL);
    const float r   = rsqrtf(var + 1e-5f);

    float4 gg = ((const float4*)g)[t];
    float4 bb = ((const float4*)b)[t];
    float4 ov;
    ov.x = dx * r * gg.x + bb.x;
    ov.y = dy * r * gg.y + bb.y;
    ov.z = dz * r * gg.z + bb.z;
    ov.w = dw * r * gg.w + bb.w;
    ((float4*)(o + row * D_MODEL))[t] = ov;
}

// ---------------------------------------------------------------------------
// Sparsemax, warp-per-row: 8 warps/block, each warp owns one SEQ=1024 row in
// registers (32 floats/lane). Bisection on tau with shfl-only reductions.
// 20 iterations: tau resolution 2^-20 on a bracket of width 1.
// ---------------------------------------------------------------------------
__global__ void __launch_bounds__(256)
sparsemax_kernel(float* __restrict__ sim)
{
    const long row  = (long)blockIdx.x * 8 + (threadIdx.x >> 5);
    const int  lane = threadIdx.x & 31;
    float4* base = (float4*)(sim + row * (long)SEQ);

    float4 z[8];
#pragma unroll
    for (int j = 0; j < 8; ++j) z[j] = base[j * 32 + lane];

    float m = -1e30f;
#pragma unroll
    for (int j = 0; j < 8; ++j)
        m = fmaxf(m, fmaxf(fmaxf(z[j].x, z[j].y), fmaxf(z[j].z, z[j].w)));
#pragma unroll
    for (int off = 16; off; off >>= 1) m = fmaxf(m, __shfl_xor_sync(~0u, m, off));

    float lo = m - 1.f, hi = m;
#pragma unroll 1
    for (int it = 0; it < 20; ++it) {
        const float tau = 0.5f * (lo + hi);
        float s = 0.f;
#pragma unroll
        for (int j = 0; j < 8; ++j) {
            s += fmaxf(z[j].x - tau, 0.f) + fmaxf(z[j].y - tau, 0.f)
               + fmaxf(z[j].z - tau, 0.f) + fmaxf(z[j].w - tau, 0.f);
        }
#pragma unroll
        for (int off = 16; off; off >>= 1) s += __shfl_xor_sync(~0u, s, off);
        if (s >= 1.f) lo = tau; else hi = tau;   // uniform across warp
    }
    const float tau = 0.5f * (lo + hi);

#pragma unroll
    for (int j = 0; j < 8; ++j) {
        float4 o;
        o.x = fmaxf(z[j].x - tau, 0.f);
        o.y = fmaxf(z[j].y - tau, 0.f);
        o.z = fmaxf(z[j].z - tau, 0.f);
        o.w = fmaxf(z[j].w - tau, 0.f);
        base[j * 32 + lane] = o;
    }
}

// ---------------------------------------------------------------------------
__global__ void __launch_bounds__(256)
geglu_kernel(const float* __restrict__ hh, float* __restrict__ o)
{
    const long i   = (long)blockIdx.x * blockDim.x + threadIdx.x;
    const long row = i >> 11;
    const int  col = (int)(i & (FF - 1));
    const float a = hh[row * (2 * FF) + col];
    const float g = hh[row * (2 * FF) + FF + col];
    o[i] = a * g * normcdff(g);
}

__global__ void __launch_bounds__(512)
pool1_kernel(const float* __restrict__ x, float* __restrict__ p)
{
    const int b = blockIdx.x, cc = blockIdx.y;
    const int d = threadIdx.x;
    float s = 0.f;
    const float* base = x + ((long)b * SEQ + cc * 128) * D_MODEL + d;
    for (int i = 0; i < 128; ++i) s += base[(long)i * D_MODEL];
    p[(b * 8 + cc) * D_MODEL + d] = s;
}

__global__ void __launch_bounds__(256)
pool2_kernel(const float* __restrict__ p, float* __restrict__ o)
{
    const int i = blockIdx.x * blockDim.x + threadIdx.x;
    const int b = i >> 9, d = i & 511;
    float s = 0.f;
#pragma unroll
    for (int cc = 0; cc < 8; ++cc) s += p[(b * 8 + cc) * D_MODEL + d];
    o[i] = s * (1.f / SEQ);
}

// ---------------------------------------------------------------------------
#define SMEM_BN128 (3 * (128 + 128) * 144)
#define SMEM_BN64  (3 * (128 +  64) * 144)

template<int BN>
static void launch_mg(const float* A, long lda, long aO, long aI,
                      const float* B, long ldb, long bO, long bI,
                      float* C, long ldc, long cO, long cI,
                      int M, int N, int K, int batches,
                      const float* bias, const float* resid,
                      const float* pos, float alpha)
{
    dim3 grid(N / BN, M / 128, batches);
    const int smem = (BN == 128) ? SMEM_BN128 : SMEM_BN64;
    mgemm_kernel<BN><<<grid, 256, smem>>>(A, lda, aO, aI, B, ldb, bO, bI,
                                          C, ldc, cO, cI, K, bias, resid, pos, alpha);
}

extern "C" void kernel_launch(void* const* d_in, const int* in_sizes, int n_in,
                              void* d_out, int out_size)
{
    const float* x      = (const float*)d_in[0];
    const float* proj_w = (const float*)d_in[1];
    const float* proj_b = (const float*)d_in[2];
    const float* pos    = (const float*)d_in[3];
    const float* ln1_g  = (const float*)d_in[4];
    const float* ln1_b  = (const float*)d_in[5];
    const float* wqkv   = (const float*)d_in[6];
    const float* wout   = (const float*)d_in[7];
    const float* bout   = (const float*)d_in[8];
    const float* ln2_g  = (const float*)d_in[9];
    const float* ln2_b  = (const float*)d_in[10];
    const float* w1     = (const float*)d_in[11];
    const float* b1     = (const float*)d_in[12];
    const float* w2     = (const float*)d_in[13];
    const float* b2     = (const float*)d_in[14];
    float* out = (float*)d_out;

    cudaFuncSetAttribute(mgemm_kernel<128>,
                         cudaFuncAttributeMaxDynamicSharedMemorySize, SMEM_BN128);
    cudaFuncSetAttribute(mgemm_kernel<64>,
                         cudaFuncAttributeMaxDynamicSharedMemorySize, SMEM_BN64);

    float *gx, *gh, *gqkv, *gsim, *gao, *ghh, *gffg, *gpool, *gwt, *gvt;
    cudaGetSymbolAddress((void**)&gx,    g_x);
    cudaGetSymbolAddress((void**)&gh,    g_h);
    cudaGetSymbolAddress((void**)&gqkv,  g_qkv);
    cudaGetSymbolAddress((void**)&gsim,  g_sim);
    cudaGetSymbolAddress((void**)&gao,   g_ao);
    cudaGetSymbolAddress((void**)&ghh,   g_hh);
    cudaGetSymbolAddress((void**)&gffg,  g_ffg);
    cudaGetSymbolAddress((void**)&gpool, g_pool);
    cudaGetSymbolAddress((void**)&gwt,   g_wt);
    cudaGetSymbolAddress((void**)&gvt,   g_vt);

    // ---- weight transposes (B operands as [N,K] row-major) ----
    transpose_kernel<<<dim3(16, 16, 1), dim3(32, 8)>>>(
        proj_w, D_MODEL, 0, 0, gwt + OFF_PROJ, D_MODEL, 0, 0);
    transpose_kernel<<<dim3(48, 16, 3), dim3(32, 8)>>>(
        wqkv, 3 * D_MODEL, 0, (long)D_MODEL * 3 * D_MODEL,
        gwt + OFF_QKV, D_MODEL, 0, (long)3 * D_MODEL * D_MODEL);
    transpose_kernel<<<dim3(16, 16, 3), dim3(32, 8)>>>(
        wout, D_MODEL, 0, (long)D_MODEL * D_MODEL,
        gwt + OFF_WOUT, D_MODEL, 0, (long)D_MODEL * D_MODEL);
    transpose_kernel<<<dim3(128, 16, 3), dim3(32, 8)>>>(
        w1, 2 * FF, 0, (long)D_MODEL * 2 * FF,
        gwt + OFF_W1, D_MODEL, 0, (long)2 * FF * D_MODEL);
    transpose_kernel<<<dim3(16, 64, 3), dim3(32, 8)>>>(
        w2, D_MODEL, 0, (long)FF * D_MODEL,
        gwt + OFF_W2, FF, 0, (long)D_MODEL * FF);

    // x = x @ proj_w + proj_b + pos
    launch_mg<128>(x, D_MODEL, 0, 0, gwt + OFF_PROJ, D_MODEL, 0, 0,
                   gx, D_MODEL, 0, 0, NROWS, D_MODEL, D_MODEL, 1,
                   proj_b, nullptr, pos, 1.f);

    const float scale = 0.125f;

    for (int l = 0; l < NDEPTH; ++l) {
        ln_kernel<<<NROWS, 128>>>(gx, ln1_g + l * D_MODEL, ln1_b + l * D_MODEL, gh);

        // qkv = h @ Wqkv
        launch_mg<128>(gh, D_MODEL, 0, 0,
                       gwt + OFF_QKV + (long)l * 3 * D_MODEL * D_MODEL, D_MODEL, 0, 0,
                       gqkv, 3 * D_MODEL, 0, 0,
                       NROWS, 3 * D_MODEL, D_MODEL, 1, nullptr, nullptr, nullptr, 1.f);

        // V^T per (b,h): [1024,64] -> [64,1024]
        transpose_kernel<<<dim3(2, 32, NB * NHEADS), dim3(32, 8)>>>(
            gqkv + 2 * D_MODEL, 3 * D_MODEL, (long)SEQ * 3 * D_MODEL, DHEAD,
            gvt, SEQ, (long)NHEADS * DHEAD * SEQ, (long)DHEAD * SEQ);

        // sim = q @ k^T * scale
        launch_mg<128>(gqkv,           3 * D_MODEL, (long)SEQ * 3 * D_MODEL, DHEAD,
                       gqkv + D_MODEL, 3 * D_MODEL, (long)SEQ * 3 * D_MODEL, DHEAD,
                       gsim, SEQ, (long)NHEADS * SEQ * SEQ, (long)SEQ * SEQ,
                       SEQ, SEQ, DHEAD, NB * NHEADS,
                       nullptr, nullptr, nullptr, scale);

        sparsemax_kernel<<<NB * NHEADS * SEQ / 8, 256>>>(gsim);

        // ao = attn @ v
        launch_mg<64>(gsim, SEQ, (long)NHEADS * SEQ * SEQ, (long)SEQ * SEQ,
                      gvt,  SEQ, (long)NHEADS * DHEAD * SEQ, (long)DHEAD * SEQ,
                      gao, D_MODEL, (long)SEQ * D_MODEL, DHEAD,
                      SEQ, DHEAD, SEQ, NB * NHEADS,
                      nullptr, nullptr, nullptr, 1.f);

        // x = x + ao @ Wout + bout
        launch_mg<128>(gao, D_MODEL, 0, 0,
                       gwt + OFF_WOUT + (long)l * D_MODEL * D_MODEL, D_MODEL, 0, 0,
                       gx, D_MODEL, 0, 0, NROWS, D_MODEL, D_MODEL, 1,
                       bout + l * D_MODEL, gx, nullptr, 1.f);

        ln_kernel<<<NROWS, 128>>>(gx, ln2_g + l * D_MODEL, ln2_b + l * D_MODEL, gh);

        // hh = h @ W1 + b1
        launch_mg<128>(gh, D_MODEL, 0, 0,
                       gwt + OFF_W1 + (long)l * 2 * FF * D_MODEL, D_MODEL, 0, 0,
                       ghh, 2 * FF, 0, 0, NROWS, 2 * FF, D_MODEL, 1,
                       b1 + (long)l * 2 * FF, nullptr, nullptr, 1.f);

        geglu_kernel<<<(NROWS * FF) / 256, 256>>>(ghh, gffg);

        // x = x + ffg @ W2 + b2
        launch_mg<128>(gffg, FF, 0, 0,
                       gwt + OFF_W2 + (long)l * D_MODEL * FF, FF, 0, 0,
                       gx, D_MODEL, 0, 0, NROWS, D_MODEL, FF, 1,
                       b2 + l * D_MODEL, gx, nullptr, 1.f);
    }

    pool1_kernel<<<dim3(NB, 8), 512>>>(gx, gpool);
    pool2_kernel<<<16, 256>>>(gpool, out);
}

// round 6
// speedup vs baseline: 2.8891x; 1.6607x over previous
#include <cuda_runtime.h>
#include <cmath>
#include <cstdint>

#define D_MODEL 512
#define SEQ     1024
#define NB      8
#define NHEADS  8
#define DHEAD   64
#define FF      2048
#define NROWS   (NB*SEQ)    /* 8192 */
#define NDEPTH  3

// ---------------- scratch (device globals; no allocation allowed) ----------
__device__ float g_x   [NROWS * D_MODEL];
__device__ float g_h   [NROWS * D_MODEL];
__device__ float g_qkv [NROWS * 3 * D_MODEL];
__device__ float g_sim [67108864];                 // 64 * 1024 * 1024
__device__ float g_ao  [NROWS * D_MODEL];
__device__ float g_hh  [NROWS * 2 * FF];
__device__ float g_ffg [NROWS * FF];
__device__ float g_pool[NB * 8 * D_MODEL];
__device__ float g_wt  [12845056];                 // transposed weights
__device__ float g_vt  [NB * NHEADS * DHEAD * SEQ];// V^T per (b,h): [64][1024]

#define OFF_PROJ 0
#define OFF_QKV  262144
#define OFF_WOUT 2621440
#define OFF_W1   3407872
#define OFF_W2   9699328

// ---------------------------------------------------------------------------
__device__ __forceinline__ void cp16(uint32_t sa, const float* ga) {
    asm volatile("cp.async.cg.shared.global [%0], [%1], 16;" :: "r"(sa), "l"(ga) : "memory");
}
__device__ __forceinline__ uint32_t smem_u32(const void* p) {
    uint32_t a;
    asm("{ .reg .u64 t; cvta.to.shared.u64 t, %1; cvt.u32.u64 %0, t; }"
        : "=r"(a) : "l"(p));
    return a;
}
__device__ __forceinline__ void cp_commit() {
    asm volatile("cp.async.commit_group;" ::: "memory");
}
// bf16x3 MMA: m16n8k16, row.col, f32 accum
__device__ __forceinline__ void mma16(float* d, const uint32_t* a, const uint32_t* b) {
    asm volatile(
        "mma.sync.aligned.m16n8k16.row.col.f32.bf16.bf16.f32 "
        "{%0,%1,%2,%3}, {%4,%5,%6,%7}, {%8,%9}, {%0,%1,%2,%3};"
        : "+f"(d[0]), "+f"(d[1]), "+f"(d[2]), "+f"(d[3])
        : "r"(a[0]), "r"(a[1]), "r"(a[2]), "r"(a[3]), "r"(b[0]), "r"(b[1]));
}
// split float2 -> packed bf16 hi pair + packed bf16 lo pair
// (v.x -> low 16 bits, v.y -> high 16 bits, matching k, k+1 fragment order)
__device__ __forceinline__ void split2(float2 v, uint32_t& hi, uint32_t& lo) {
    asm("cvt.rn.bf16x2.f32 %0, %1, %2;" : "=r"(hi) : "f"(v.y), "f"(v.x));
    const float h0 = __uint_as_float(hi << 16);
    const float h1 = __uint_as_float(hi & 0xFFFF0000u);
    const float r0 = v.x - h0;
    const float r1 = v.y - h1;
    asm("cvt.rn.bf16x2.f32 %0, %1, %2;" : "=r"(lo) : "f"(r1), "f"(r0));
}

// ---------------------------------------------------------------------------
// bf16x3 mma.sync GEMM:  C[M,N] = alpha * A[M,K] @ Bt[N,K]^T (+bias+resid+pos)
// A row-major [M,K], Bt row-major [N,K]. M%128==0, N%BN==0, K%32==0.
// Batched via blockIdx.z -> (zo=z>>3, zi=z&7).
// smem rows padded to 160B (PITCH=40 floats) -> float2 fragment loads
// conflict-free. 2-stage cp.async double buffer.
// ---------------------------------------------------------------------------
template<int BN>
__global__ void __launch_bounds__(256, 2)
mgemm_kernel(const float* __restrict__ A, long lda, long aO, long aI,
             const float* __restrict__ B, long ldb, long bO, long bI,
             float* __restrict__ C, long ldc, long cO, long cI,
             int K,
             const float* __restrict__ bias,
             const float* __restrict__ resid,
             const float* __restrict__ pos,
             float alpha)
{
    constexpr int BM = 128;
    constexpr int WN = BN / 2;       // warp tile: 32 x WN (4x2 warp grid)
    constexpr int NI = WN / 8;       // n-tiles per warp
    constexpr int PITCH = 40;        // floats per smem row (160B)
    constexpr int STAGE_F = (BM + BN) * PITCH;

    extern __shared__ float smem[];

    const int z = blockIdx.z, zo = z >> 3, zi = z & 7;
    A += zo * aO + zi * aI;
    B += zo * bO + zi * bI;
    C += zo * cO + zi * cI;
    const float* Rz = resid ? resid + zo * cO + zi * cI : nullptr;

    const long m0 = (long)blockIdx.y * BM;
    const long n0 = (long)blockIdx.x * BN;
    A += m0 * lda;
    B += n0 * ldb;

    const int t    = threadIdx.x;
    const int wid  = t >> 5, lane = t & 31;
    const int wr   = wid & 3, wc = wid >> 2;
    const int g    = lane >> 2, c = lane & 3;

    const uint32_t sbase = smem_u32(smem);
    const int niter = K >> 5;        // chunks of K=32

    auto load_stage = [&](int s, int kc) {
        const uint32_t sA = sbase + (uint32_t)(s * STAGE_F) * 4u;
        const uint32_t sB = sA + BM * PITCH * 4u;
        const float* ga = A + kc * 32;
        const float* gb = B + kc * 32;
        const int r0  = t >> 3;
        const int seg = (t & 7) * 16;
#pragma unroll
        for (int p = 0; p < BM / 32; ++p) {
            const int r = p * 32 + r0;
            cp16(sA + r * 160 + seg, ga + (long)r * lda + (t & 7) * 4);
        }
#pragma unroll
        for (int p = 0; p < BN / 32; ++p) {
            const int r = p * 32 + r0;
            cp16(sB + r * 160 + seg, gb + (long)r * ldb + (t & 7) * 4);
        }
        cp_commit();
    };

    float acc[2][NI][4];
#pragma unroll
    for (int mi = 0; mi < 2; ++mi)
#pragma unroll
        for (int ni = 0; ni < NI; ++ni)
#pragma unroll
            for (int j = 0; j < 4; ++j) acc[mi][ni][j] = 0.f;

    load_stage(0, 0);

    for (int i = 0; i < niter; ++i) {
        if (i + 1 < niter) {
            load_stage((i + 1) & 1, i + 1);
            asm volatile("cp.async.wait_group 1;" ::: "memory");
        } else {
            asm volatile("cp.async.wait_group 0;" ::: "memory");
        }
        __syncthreads();

        const float* As = smem + (i & 1) * STAGE_F;
        const float* Bs = As + BM * PITCH;

#pragma unroll
        for (int ks = 0; ks < 2; ++ks) {      // two k16 steps per K=32 chunk
            const int kk = ks * 16 + 2 * c;
            uint32_t ah[2][4], al[2][4];
#pragma unroll
            for (int mi = 0; mi < 2; ++mi) {
                const int rb = (wr * 32 + mi * 16 + g) * PITCH + kk;
                split2(*(const float2*)&As[rb],                 ah[mi][0], al[mi][0]);
                split2(*(const float2*)&As[rb + 8 * PITCH],     ah[mi][1], al[mi][1]);
                split2(*(const float2*)&As[rb + 8],             ah[mi][2], al[mi][2]);
                split2(*(const float2*)&As[rb + 8 * PITCH + 8], ah[mi][3], al[mi][3]);
            }
            uint32_t bh[NI][2], bl[NI][2];
#pragma unroll
            for (int ni = 0; ni < NI; ++ni) {
                const int rb = (wc * WN + ni * 8 + g) * PITCH + kk;
                split2(*(const float2*)&Bs[rb],     bh[ni][0], bl[ni][0]);
                split2(*(const float2*)&Bs[rb + 8], bh[ni][1], bl[ni][1]);
            }
#pragma unroll
            for (int mi = 0; mi < 2; ++mi)
#pragma unroll
                for (int ni = 0; ni < NI; ++ni) {
                    mma16(acc[mi][ni], al[mi], bh[ni]);
                    mma16(acc[mi][ni], ah[mi], bl[ni]);
                    mma16(acc[mi][ni], ah[mi], bh[ni]);
                }
        }
        __syncthreads();
    }

    // ---- epilogue: direct fragment stores (float2) ----
#pragma unroll
    for (int mi = 0; mi < 2; ++mi) {
#pragma unroll
        for (int ni = 0; ni < NI; ++ni) {
            const long col = n0 + wc * WN + ni * 8 + 2 * c;
#pragma unroll
            for (int h = 0; h < 2; ++h) {
                const long row = m0 + wr * 32 + mi * 16 + g + h * 8;
                float vx = acc[mi][ni][2 * h]     * alpha;
                float vy = acc[mi][ni][2 * h + 1] * alpha;
                if (bias) {
                    float2 bv = *(const float2*)&bias[col];
                    vx += bv.x; vy += bv.y;
                }
                const long off = row * ldc + col;
                if (Rz) {
                    float2 rv = *(const float2*)&Rz[off];
                    vx += rv.x; vy += rv.y;
                }
                if (pos) {
                    float2 pv = *(const float2*)&pos[(row & (SEQ - 1)) * D_MODEL + col];
                    vx += pv.x; vy += pv.y;
                }
                *(float2*)&C[off] = make_float2(vx, vy);
            }
        }
    }
}

// ---------------------------------------------------------------------------
__global__ void __launch_bounds__(256)
transpose_kernel(const float* __restrict__ in, long ldi, long iO, long iI,
                 float* __restrict__ out, long ldo, long oO, long oI)
{
    __shared__ float tile[32][33];
    const int z = blockIdx.z;
    in  += (z >> 3) * iO + (z & 7) * iI;
    out += (z >> 3) * oO + (z & 7) * oI;
    const long r0 = (long)blockIdx.y * 32, c0 = (long)blockIdx.x * 32;
#pragma unroll
    for (int i = 0; i < 32; i += 8)
        tile[threadIdx.y + i][threadIdx.x] =
            in[(r0 + threadIdx.y + i) * ldi + c0 + threadIdx.x];
    __syncthreads();
#pragma unroll
    for (int i = 0; i < 32; i += 8)
        out[(c0 + threadIdx.y + i) * ldo + r0 + threadIdx.x] =
            tile[threadIdx.x][threadIdx.y + i];
}

// ---------------------------------------------------------------------------
__global__ void __launch_bounds__(128)
ln_kernel(const float* __restrict__ x, const float* __restrict__ g,
          const float* __restrict__ b, float* __restrict__ o)
{
    __shared__ float sh[4];
    const long row = blockIdx.x;
    const int  t   = threadIdx.x;
    float4 v = ((const float4*)(x + row * D_MODEL))[t];

    float s = v.x + v.y + v.z + v.w;
#pragma unroll
    for (int off = 16; off; off >>= 1) s += __shfl_xor_sync(~0u, s, off);
    if ((t & 31) == 0) sh[t >> 5] = s;
    __syncthreads();
    const float mu = (sh[0] + sh[1] + sh[2] + sh[3]) * (1.f / D_MODEL);

    const float dx = v.x - mu, dy = v.y - mu, dz = v.z - mu, dw = v.w - mu;
    float s2 = dx * dx + dy * dy + dz * dz + dw * dw;
#pragma unroll
    for (int off = 16; off; off >>= 1) s2 += __shfl_xor_sync(~0u, s2, off);
    __syncthreads();
    if ((t & 31) == 0) sh[t >> 5] = s2;
    __syncthreads();
    const float var = (sh[0] + sh[1] + sh[2] + sh[3]) * (1.f / D_MODEL);
    const float r   = rsqrtf(var + 1e-5f);

    float4 gg = ((const float4*)g)[t];
    float4 bb = ((const float4*)b)[t];
    float4 ov;
    ov.x = dx * r * gg.x + bb.x;
    ov.y = dy * r * gg.y + bb.y;
    ov.z = dz * r * gg.z + bb.z;
    ov.w = dw * r * gg.w + bb.w;
    ((float4*)(o + row * D_MODEL))[t] = ov;
}

// ---------------------------------------------------------------------------
// Sparsemax, warp-per-row (registers + shfl), 20-iter bisection on tau.
// ---------------------------------------------------------------------------
__global__ void __launch_bounds__(256)
sparsemax_kernel(float* __restrict__ sim)
{
    const long row  = (long)blockIdx.x * 8 + (threadIdx.x >> 5);
    const int  lane = threadIdx.x & 31;
    float4* base = (float4*)(sim + row * (long)SEQ);

    float4 z[8];
#pragma unroll
    for (int j = 0; j < 8; ++j) z[j] = base[j * 32 + lane];

    float m = -1e30f;
#pragma unroll
    for (int j = 0; j < 8; ++j)
        m = fmaxf(m, fmaxf(fmaxf(z[j].x, z[j].y), fmaxf(z[j].z, z[j].w)));
#pragma unroll
    for (int off = 16; off; off >>= 1) m = fmaxf(m, __shfl_xor_sync(~0u, m, off));

    float lo = m - 1.f, hi = m;
#pragma unroll 1
    for (int it = 0; it < 20; ++it) {
        const float tau = 0.5f * (lo + hi);
        float s = 0.f;
#pragma unroll
        for (int j = 0; j < 8; ++j) {
            s += fmaxf(z[j].x - tau, 0.f) + fmaxf(z[j].y - tau, 0.f)
               + fmaxf(z[j].z - tau, 0.f) + fmaxf(z[j].w - tau, 0.f);
        }
#pragma unroll
        for (int off = 16; off; off >>= 1) s += __shfl_xor_sync(~0u, s, off);
        if (s >= 1.f) lo = tau; else hi = tau;
    }
    const float tau = 0.5f * (lo + hi);

#pragma unroll
    for (int j = 0; j < 8; ++j) {
        float4 o;
        o.x = fmaxf(z[j].x - tau, 0.f);
        o.y = fmaxf(z[j].y - tau, 0.f);
        o.z = fmaxf(z[j].z - tau, 0.f);
        o.w = fmaxf(z[j].w - tau, 0.f);
        base[j * 32 + lane] = o;
    }
}

// ---------------------------------------------------------------------------
__global__ void __launch_bounds__(256)
geglu_kernel(const float* __restrict__ hh, float* __restrict__ o)
{
    const long i   = (long)blockIdx.x * blockDim.x + threadIdx.x;
    const long row = i >> 11;
    const int  col = (int)(i & (FF - 1));
    const float a = hh[row * (2 * FF) + col];
    const float g = hh[row * (2 * FF) + FF + col];
    o[i] = a * g * normcdff(g);
}

__global__ void __launch_bounds__(512)
pool1_kernel(const float* __restrict__ x, float* __restrict__ p)
{
    const int b = blockIdx.x, cc = blockIdx.y;
    const int d = threadIdx.x;
    float s = 0.f;
    const float* base = x + ((long)b * SEQ + cc * 128) * D_MODEL + d;
    for (int i = 0; i < 128; ++i) s += base[(long)i * D_MODEL];
    p[(b * 8 + cc) * D_MODEL + d] = s;
}

__global__ void __launch_bounds__(256)
pool2_kernel(const float* __restrict__ p, float* __restrict__ o)
{
    const int i = blockIdx.x * blockDim.x + threadIdx.x;
    const int b = i >> 9, d = i & 511;
    float s = 0.f;
#pragma unroll
    for (int cc = 0; cc < 8; ++cc) s += p[(b * 8 + cc) * D_MODEL + d];
    o[i] = s * (1.f / SEQ);
}

// ---------------------------------------------------------------------------
#define SMEM_BN128 (2 * (128 + 128) * 160)
#define SMEM_BN64  (2 * (128 +  64) * 160)

template<int BN>
static void launch_mg(const float* A, long lda, long aO, long aI,
                      const float* B, long ldb, long bO, long bI,
                      float* C, long ldc, long cO, long cI,
                      int M, int N, int K, int batches,
                      const float* bias, const float* resid,
                      const float* pos, float alpha)
{
    dim3 grid(N / BN, M / 128, batches);
    const int smem = (BN == 128) ? SMEM_BN128 : SMEM_BN64;
    mgemm_kernel<BN><<<grid, 256, smem>>>(A, lda, aO, aI, B, ldb, bO, bI,
                                          C, ldc, cO, cI, K, bias, resid, pos, alpha);
}

extern "C" void kernel_launch(void* const* d_in, const int* in_sizes, int n_in,
                              void* d_out, int out_size)
{
    const float* x      = (const float*)d_in[0];
    const float* proj_w = (const float*)d_in[1];
    const float* proj_b = (const float*)d_in[2];
    const float* pos    = (const float*)d_in[3];
    const float* ln1_g  = (const float*)d_in[4];
    const float* ln1_b  = (const float*)d_in[5];
    const float* wqkv   = (const float*)d_in[6];
    const float* wout   = (const float*)d_in[7];
    const float* bout   = (const float*)d_in[8];
    const float* ln2_g  = (const float*)d_in[9];
    const float* ln2_b  = (const float*)d_in[10];
    const float* w1     = (const float*)d_in[11];
    const float* b1     = (const float*)d_in[12];
    const float* w2     = (const float*)d_in[13];
    const float* b2     = (const float*)d_in[14];
    float* out = (float*)d_out;

    cudaFuncSetAttribute(mgemm_kernel<128>,
                         cudaFuncAttributeMaxDynamicSharedMemorySize, SMEM_BN128);
    cudaFuncSetAttribute(mgemm_kernel<64>,
                         cudaFuncAttributeMaxDynamicSharedMemorySize, SMEM_BN64);

    float *gx, *gh, *gqkv, *gsim, *gao, *ghh, *gffg, *gpool, *gwt, *gvt;
    cudaGetSymbolAddress((void**)&gx,    g_x);
    cudaGetSymbolAddress((void**)&gh,    g_h);
    cudaGetSymbolAddress((void**)&gqkv,  g_qkv);
    cudaGetSymbolAddress((void**)&gsim,  g_sim);
    cudaGetSymbolAddress((void**)&gao,   g_ao);
    cudaGetSymbolAddress((void**)&ghh,   g_hh);
    cudaGetSymbolAddress((void**)&gffg,  g_ffg);
    cudaGetSymbolAddress((void**)&gpool, g_pool);
    cudaGetSymbolAddress((void**)&gwt,   g_wt);
    cudaGetSymbolAddress((void**)&gvt,   g_vt);

    // ---- weight transposes (B operands as [N,K] row-major) ----
    transpose_kernel<<<dim3(16, 16, 1), dim3(32, 8)>>>(
        proj_w, D_MODEL, 0, 0, gwt + OFF_PROJ, D_MODEL, 0, 0);
    transpose_kernel<<<dim3(48, 16, 3), dim3(32, 8)>>>(
        wqkv, 3 * D_MODEL, 0, (long)D_MODEL * 3 * D_MODEL,
        gwt + OFF_QKV, D_MODEL, 0, (long)3 * D_MODEL * D_MODEL);
    transpose_kernel<<<dim3(16, 16, 3), dim3(32, 8)>>>(
        wout, D_MODEL, 0, (long)D_MODEL * D_MODEL,
        gwt + OFF_WOUT, D_MODEL, 0, (long)D_MODEL * D_MODEL);
    transpose_kernel<<<dim3(128, 16, 3), dim3(32, 8)>>>(
        w1, 2 * FF, 0, (long)D_MODEL * 2 * FF,
        gwt + OFF_W1, D_MODEL, 0, (long)2 * FF * D_MODEL);
    transpose_kernel<<<dim3(16, 64, 3), dim3(32, 8)>>>(
        w2, D_MODEL, 0, (long)FF * D_MODEL,
        gwt + OFF_W2, FF, 0, (long)D_MODEL * FF);

    // x = x @ proj_w + proj_b + pos
    launch_mg<128>(x, D_MODEL, 0, 0, gwt + OFF_PROJ, D_MODEL, 0, 0,
                   gx, D_MODEL, 0, 0, NROWS, D_MODEL, D_MODEL, 1,
                   proj_b, nullptr, pos, 1.f);

    const float scale = 0.125f;

    for (int l = 0; l < NDEPTH; ++l) {
        ln_kernel<<<NROWS, 128>>>(gx, ln1_g + l * D_MODEL, ln1_b + l * D_MODEL, gh);

        // qkv = h @ Wqkv
        launch_mg<128>(gh, D_MODEL, 0, 0,
                       gwt + OFF_QKV + (long)l * 3 * D_MODEL * D_MODEL, D_MODEL, 0, 0,
                       gqkv, 3 * D_MODEL, 0, 0,
                       NROWS, 3 * D_MODEL, D_MODEL, 1, nullptr, nullptr, nullptr, 1.f);

        // V^T per (b,h): [1024,64] -> [64,1024]
        transpose_kernel<<<dim3(2, 32, NB * NHEADS), dim3(32, 8)>>>(
            gqkv + 2 * D_MODEL, 3 * D_MODEL, (long)SEQ * 3 * D_MODEL, DHEAD,
            gvt, SEQ, (long)NHEADS * DHEAD * SEQ, (long)DHEAD * SEQ);

        // sim = q @ k^T * scale
        launch_mg<128>(gqkv,           3 * D_MODEL, (long)SEQ * 3 * D_MODEL, DHEAD,
                       gqkv + D_MODEL, 3 * D_MODEL, (long)SEQ * 3 * D_MODEL, DHEAD,
                       gsim, SEQ, (long)NHEADS * SEQ * SEQ, (long)SEQ * SEQ,
                       SEQ, SEQ, DHEAD, NB * NHEADS,
                       nullptr, nullptr, nullptr, scale);

        sparsemax_kernel<<<NB * NHEADS * SEQ / 8, 256>>>(gsim);

        // ao = attn @ v
        launch_mg<64>(gsim, SEQ, (long)NHEADS * SEQ * SEQ, (long)SEQ * SEQ,
                      gvt,  SEQ, (long)NHEADS * DHEAD * SEQ, (long)DHEAD * SEQ,
                      gao, D_MODEL, (long)SEQ * D_MODEL, DHEAD,
                      SEQ, DHEAD, SEQ, NB * NHEADS,
                      nullptr, nullptr, nullptr, 1.f);

        // x = x + ao @ Wout + bout
        launch_mg<128>(gao, D_MODEL, 0, 0,
                       gwt + OFF_WOUT + (long)l * D_MODEL * D_MODEL, D_MODEL, 0, 0,
                       gx, D_MODEL, 0, 0, NROWS, D_MODEL, D_MODEL, 1,
                       bout + l * D_MODEL, gx, nullptr, 1.f);

        ln_kernel<<<NROWS, 128>>>(gx, ln2_g + l * D_MODEL, ln2_b + l * D_MODEL, gh);

        // hh = h @ W1 + b1
        launch_mg<128>(gh, D_MODEL, 0, 0,
                       gwt + OFF_W1 + (long)l * 2 * FF * D_MODEL, D_MODEL, 0, 0,
                       ghh, 2 * FF, 0, 0, NROWS, 2 * FF, D_MODEL, 1,
                       b1 + (long)l * 2 * FF, nullptr, nullptr, 1.f);

        geglu_kernel<<<(NROWS * FF) / 256, 256>>>(ghh, gffg);

        // x = x + ffg @ W2 + b2
        launch_mg<128>(gffg, FF, 0, 0,
                       gwt + OFF_W2 + (long)l * D_MODEL * FF, FF, 0, 0,
                       gx, D_MODEL, 0, 0, NROWS, D_MODEL, FF, 1,
                       b2 + l * D_MODEL, gx, nullptr, 1.f);
    }

    pool1_kernel<<<dim3(NB, 8), 512>>>(gx, gpool);
    pool2_kernel<<<16, 256>>>(gpool, out);
}

// round 7
// speedup vs baseline: 3.0642x; 1.0606x over previous
#include <cuda_runtime.h>
#include <cmath>
#include <cstdint>

#define D_MODEL 512
#define SEQ     1024
#define NB      8
#define NHEADS  8
#define DHEAD   64
#define FF      2048
#define NROWS   (NB*SEQ)    /* 8192 */
#define NDEPTH  3

// ---------------- scratch (device globals; no allocation allowed) ----------
__device__ float g_x   [NROWS * D_MODEL];
__device__ float g_h   [NROWS * D_MODEL];
__device__ float g_qkv [NROWS * 3 * D_MODEL];
__device__ float g_sim [67108864];                 // 64 * 1024 * 1024
__device__ float g_ao  [NROWS * D_MODEL];
__device__ float g_ffg [NROWS * FF];
__device__ float g_pool[NB * 8 * D_MODEL];
__device__ float g_wt  [12845056];                 // transposed weights
__device__ float g_vt  [NB * NHEADS * DHEAD * SEQ];// V^T per (b,h): [64][1024]

#define OFF_PROJ 0
#define OFF_QKV  262144
#define OFF_WOUT 2621440
#define OFF_W1   3407872
#define OFF_W2   9699328

// ---------------------------------------------------------------------------
__device__ __forceinline__ void cp16(uint32_t sa, const float* ga) {
    asm volatile("cp.async.cg.shared.global [%0], [%1], 16;" :: "r"(sa), "l"(ga) : "memory");
}
__device__ __forceinline__ uint32_t smem_u32(const void* p) {
    uint32_t a;
    asm("{ .reg .u64 t; cvta.to.shared.u64 t, %1; cvt.u32.u64 %0, t; }"
        : "=r"(a) : "l"(p));
    return a;
}
__device__ __forceinline__ void cp_commit() {
    asm volatile("cp.async.commit_group;" ::: "memory");
}
// bf16x3 MMA: m16n8k16, row.col, f32 accum
__device__ __forceinline__ void mma16(float* d, const uint32_t* a, const uint32_t* b) {
    asm volatile(
        "mma.sync.aligned.m16n8k16.row.col.f32.bf16.bf16.f32 "
        "{%0,%1,%2,%3}, {%4,%5,%6,%7}, {%8,%9}, {%0,%1,%2,%3};"
        : "+f"(d[0]), "+f"(d[1]), "+f"(d[2]), "+f"(d[3])
        : "r"(a[0]), "r"(a[1]), "r"(a[2]), "r"(a[3]), "r"(b[0]), "r"(b[1]));
}
// split float2 -> packed bf16 hi pair + packed bf16 lo pair
__device__ __forceinline__ void split2(float2 v, uint32_t& hi, uint32_t& lo) {
    asm("cvt.rn.bf16x2.f32 %0, %1, %2;" : "=r"(hi) : "f"(v.y), "f"(v.x));
    const float h0 = __uint_as_float(hi << 16);
    const float h1 = __uint_as_float(hi & 0xFFFF0000u);
    const float r0 = v.x - h0;
    const float r1 = v.y - h1;
    asm("cvt.rn.bf16x2.f32 %0, %1, %2;" : "=r"(lo) : "f"(r1), "f"(r0));
}

// ---------------------------------------------------------------------------
// bf16x3 mma.sync GEMM:  C[M,N] = alpha * A[M,K] @ Bt[N,K]^T (+bias+resid+pos)
// GEGLU=true: B columns are interleaved (a0,g0,a1,g1,...); epilogue computes
// ff = (a + bias_a) * gelu(g + bias_g) and stores ONE float at C[row, col/2]
// (ldc = FF). bias points at the un-permuted b1 (a at [j], g at [j+FF]).
// ---------------------------------------------------------------------------
template<int BN, bool GEGLU>
__global__ void __launch_bounds__(256, 2)
mgemm_kernel(const float* __restrict__ A, long lda, long aO, long aI,
             const float* __restrict__ B, long ldb, long bO, long bI,
             float* __restrict__ C, long ldc, long cO, long cI,
             int K,
             const float* __restrict__ bias,
             const float* __restrict__ resid,
             const float* __restrict__ pos,
             float alpha)
{
    constexpr int BM = 128;
    constexpr int WN = BN / 2;       // warp tile: 32 x WN (4x2 warp grid)
    constexpr int NI = WN / 8;       // n-tiles per warp
    constexpr int PITCH = 40;        // floats per smem row (160B)
    constexpr int STAGE_F = (BM + BN) * PITCH;

    extern __shared__ float smem[];

    const int z = blockIdx.z, zo = z >> 3, zi = z & 7;
    A += zo * aO + zi * aI;
    B += zo * bO + zi * bI;
    C += zo * cO + zi * cI;
    const float* Rz = resid ? resid + zo * cO + zi * cI : nullptr;

    const long m0 = (long)blockIdx.y * BM;
    const long n0 = (long)blockIdx.x * BN;
    A += m0 * lda;
    B += n0 * ldb;

    const int t    = threadIdx.x;
    const int wid  = t >> 5, lane = t & 31;
    const int wr   = wid & 3, wc = wid >> 2;
    const int g    = lane >> 2, c = lane & 3;

    const uint32_t sbase = smem_u32(smem);
    const int niter = K >> 5;        // chunks of K=32

    auto load_stage = [&](int s, int kc) {
        const uint32_t sA = sbase + (uint32_t)(s * STAGE_F) * 4u;
        const uint32_t sB = sA + BM * PITCH * 4u;
        const float* ga = A + kc * 32;
        const float* gb = B + kc * 32;
        const int r0  = t >> 3;
        const int seg = (t & 7) * 16;
#pragma unroll
        for (int p = 0; p < BM / 32; ++p) {
            const int r = p * 32 + r0;
            cp16(sA + r * 160 + seg, ga + (long)r * lda + (t & 7) * 4);
        }
#pragma unroll
        for (int p = 0; p < BN / 32; ++p) {
            const int r = p * 32 + r0;
            cp16(sB + r * 160 + seg, gb + (long)r * ldb + (t & 7) * 4);
        }
        cp_commit();
    };

    float acc[2][NI][4];
#pragma unroll
    for (int mi = 0; mi < 2; ++mi)
#pragma unroll
        for (int ni = 0; ni < NI; ++ni)
#pragma unroll
            for (int j = 0; j < 4; ++j) acc[mi][ni][j] = 0.f;

    load_stage(0, 0);

    for (int i = 0; i < niter; ++i) {
        if (i + 1 < niter) {
            load_stage((i + 1) & 1, i + 1);
            asm volatile("cp.async.wait_group 1;" ::: "memory");
        } else {
            asm volatile("cp.async.wait_group 0;" ::: "memory");
        }
        __syncthreads();

        const float* As = smem + (i & 1) * STAGE_F;
        const float* Bs = As + BM * PITCH;

#pragma unroll
        for (int ks = 0; ks < 2; ++ks) {      // two k16 steps per K=32 chunk
            const int kk = ks * 16 + 2 * c;
            uint32_t ah[2][4], al[2][4];
#pragma unroll
            for (int mi = 0; mi < 2; ++mi) {
                const int rb = (wr * 32 + mi * 16 + g) * PITCH + kk;
                split2(*(const float2*)&As[rb],                 ah[mi][0], al[mi][0]);
                split2(*(const float2*)&As[rb + 8 * PITCH],     ah[mi][1], al[mi][1]);
                split2(*(const float2*)&As[rb + 8],             ah[mi][2], al[mi][2]);
                split2(*(const float2*)&As[rb + 8 * PITCH + 8], ah[mi][3], al[mi][3]);
            }
            uint32_t bh[NI][2], bl[NI][2];
#pragma unroll
            for (int ni = 0; ni < NI; ++ni) {
                const int rb = (wc * WN + ni * 8 + g) * PITCH + kk;
                split2(*(const float2*)&Bs[rb],     bh[ni][0], bl[ni][0]);
                split2(*(const float2*)&Bs[rb + 8], bh[ni][1], bl[ni][1]);
            }
#pragma unroll
            for (int mi = 0; mi < 2; ++mi)
#pragma unroll
                for (int ni = 0; ni < NI; ++ni) {
                    mma16(acc[mi][ni], al[mi], bh[ni]);
                    mma16(acc[mi][ni], ah[mi], bl[ni]);
                    mma16(acc[mi][ni], ah[mi], bh[ni]);
                }
        }
        __syncthreads();
    }

    // ---- epilogue ----
#pragma unroll
    for (int mi = 0; mi < 2; ++mi) {
#pragma unroll
        for (int ni = 0; ni < NI; ++ni) {
            const long col = n0 + wc * WN + ni * 8 + 2 * c;
#pragma unroll
            for (int h = 0; h < 2; ++h) {
                const long row = m0 + wr * 32 + mi * 16 + g + h * 8;
                float vx = acc[mi][ni][2 * h];
                float vy = acc[mi][ni][2 * h + 1];
                if (GEGLU) {
                    // vx = a (even interleaved col), vy = g (odd)
                    const long j = col >> 1;
                    const float a  = vx + bias[j];
                    const float gg = vy + bias[j + FF];
                    C[row * ldc + j] = a * gg * normcdff(gg);
                } else {
                    vx *= alpha; vy *= alpha;
                    if (bias) {
                        float2 bv = *(const float2*)&bias[col];
                        vx += bv.x; vy += bv.y;
                    }
                    const long off = row * ldc + col;
                    if (Rz) {
                        float2 rv = *(const float2*)&Rz[off];
                        vx += rv.x; vy += rv.y;
                    }
                    if (pos) {
                        float2 pv = *(const float2*)&pos[(row & (SEQ - 1)) * D_MODEL + col];
                        vx += pv.x; vy += pv.y;
                    }
                    *(float2*)&C[off] = make_float2(vx, vy);
                }
            }
        }
    }
}

// ---------------------------------------------------------------------------
__global__ void __launch_bounds__(256)
transpose_kernel(const float* __restrict__ in, long ldi, long iO, long iI,
                 float* __restrict__ out, long ldo, long oO, long oI)
{
    __shared__ float tile[32][33];
    const int z = blockIdx.z;
    in  += (z >> 3) * iO + (z & 7) * iI;
    out += (z >> 3) * oO + (z & 7) * oI;
    const long r0 = (long)blockIdx.y * 32, c0 = (long)blockIdx.x * 32;
#pragma unroll
    for (int i = 0; i < 32; i += 8)
        tile[threadIdx.y + i][threadIdx.x] =
            in[(r0 + threadIdx.y + i) * ldi + c0 + threadIdx.x];
    __syncthreads();
#pragma unroll
    for (int i = 0; i < 32; i += 8)
        out[(c0 + threadIdx.y + i) * ldo + r0 + threadIdx.x] =
            tile[threadIdx.x][threadIdx.y + i];
}

// W1 transpose with a/g interleave: in = w1[l] as [512, 4096]; out row for
// orig col n is (n < FF) ? 2n : 2(n-FF)+1; out is [4096, 512].
__global__ void __launch_bounds__(256)
transpose_w1_kernel(const float* __restrict__ in, float* __restrict__ out)
{
    __shared__ float tile[32][33];
    const int z = blockIdx.z;                   // layer
    in  += (long)z * D_MODEL * (2 * FF);
    out += (long)z * (2 * FF) * D_MODEL;
    const long r0 = (long)blockIdx.y * 32;      // k block (0..511)
    const long c0 = (long)blockIdx.x * 32;      // n block (0..4095)
#pragma unroll
    for (int i = 0; i < 32; i += 8)
        tile[threadIdx.y + i][threadIdx.x] =
            in[(r0 + threadIdx.y + i) * (2 * FF) + c0 + threadIdx.x];
    __syncthreads();
#pragma unroll
    for (int i = 0; i < 32; i += 8) {
        const long n = c0 + threadIdx.y + i;
        const long r_out = (n < FF) ? 2 * n : 2 * (n - FF) + 1;
        out[r_out * D_MODEL + r0 + threadIdx.x] = tile[threadIdx.x][threadIdx.y + i];
    }
}

// ---------------------------------------------------------------------------
__global__ void __launch_bounds__(128)
ln_kernel(const float* __restrict__ x, const float* __restrict__ g,
          const float* __restrict__ b, float* __restrict__ o)
{
    __shared__ float sh[4];
    const long row = blockIdx.x;
    const int  t   = threadIdx.x;
    float4 v = ((const float4*)(x + row * D_MODEL))[t];

    float s = v.x + v.y + v.z + v.w;
#pragma unroll
    for (int off = 16; off; off >>= 1) s += __shfl_xor_sync(~0u, s, off);
    if ((t & 31) == 0) sh[t >> 5] = s;
    __syncthreads();
    const float mu = (sh[0] + sh[1] + sh[2] + sh[3]) * (1.f / D_MODEL);

    const float dx = v.x - mu, dy = v.y - mu, dz = v.z - mu, dw = v.w - mu;
    float s2 = dx * dx + dy * dy + dz * dz + dw * dw;
#pragma unroll
    for (int off = 16; off; off >>= 1) s2 += __shfl_xor_sync(~0u, s2, off);
    __syncthreads();
    if ((t & 31) == 0) sh[t >> 5] = s2;
    __syncthreads();
    const float var = (sh[0] + sh[1] + sh[2] + sh[3]) * (1.f / D_MODEL);
    const float r   = rsqrtf(var + 1e-5f);

    float4 gg = ((const float4*)g)[t];
    float4 bb = ((const float4*)b)[t];
    float4 ov;
    ov.x = dx * r * gg.x + bb.x;
    ov.y = dy * r * gg.y + bb.y;
    ov.z = dz * r * gg.z + bb.z;
    ov.w = dw * r * gg.w + bb.w;
    ((float4*)(o + row * D_MODEL))[t] = ov;
}

// ---------------------------------------------------------------------------
// Sparsemax, warp-per-row: 15-iter bisection + one exact Michelot refinement
// (tau = (sum_{z>tau} z - 1)/count, exact once the active set is pinned).
// ---------------------------------------------------------------------------
__global__ void __launch_bounds__(256)
sparsemax_kernel(float* __restrict__ sim)
{
    const long row  = (long)blockIdx.x * 8 + (threadIdx.x >> 5);
    const int  lane = threadIdx.x & 31;
    float4* base = (float4*)(sim + row * (long)SEQ);

    float4 z[8];
#pragma unroll
    for (int j = 0; j < 8; ++j) z[j] = base[j * 32 + lane];

    float m = -1e30f;
#pragma unroll
    for (int j = 0; j < 8; ++j)
        m = fmaxf(m, fmaxf(fmaxf(z[j].x, z[j].y), fmaxf(z[j].z, z[j].w)));
#pragma unroll
    for (int off = 16; off; off >>= 1) m = fmaxf(m, __shfl_xor_sync(~0u, m, off));

    float lo = m - 1.f, hi = m;
#pragma unroll 1
    for (int it = 0; it < 15; ++it) {
        const float tau = 0.5f * (lo + hi);
        float s = 0.f;
#pragma unroll
        for (int j = 0; j < 8; ++j) {
            s += fmaxf(z[j].x - tau, 0.f) + fmaxf(z[j].y - tau, 0.f)
               + fmaxf(z[j].z - tau, 0.f) + fmaxf(z[j].w - tau, 0.f);
        }
#pragma unroll
        for (int off = 16; off; off >>= 1) s += __shfl_xor_sync(~0u, s, off);
        if (s >= 1.f) lo = tau; else hi = tau;
    }
    // exact refinement on the pinned active set
    {
        const float tau = 0.5f * (lo + hi);
        float s = 0.f, k = 0.f;
#pragma unroll
        for (int j = 0; j < 8; ++j) {
            if (z[j].x > tau) { s += z[j].x; k += 1.f; }
            if (z[j].y > tau) { s += z[j].y; k += 1.f; }
            if (z[j].z > tau) { s += z[j].z; k += 1.f; }
            if (z[j].w > tau) { s += z[j].w; k += 1.f; }
        }
#pragma unroll
        for (int off = 16; off; off >>= 1) {
            s += __shfl_xor_sync(~0u, s, off);
            k += __shfl_xor_sync(~0u, k, off);
        }
        const float tau_x = (s - 1.f) / k;
#pragma unroll
        for (int j = 0; j < 8; ++j) {
            float4 o;
            o.x = fmaxf(z[j].x - tau_x, 0.f);
            o.y = fmaxf(z[j].y - tau_x, 0.f);
            o.z = fmaxf(z[j].z - tau_x, 0.f);
            o.w = fmaxf(z[j].w - tau_x, 0.f);
            base[j * 32 + lane] = o;
        }
    }
}

// ---------------------------------------------------------------------------
__global__ void __launch_bounds__(512)
pool1_kernel(const float* __restrict__ x, float* __restrict__ p)
{
    const int b = blockIdx.x, cc = blockIdx.y;
    const int d = threadIdx.x;
    float s = 0.f;
    const float* base = x + ((long)b * SEQ + cc * 128) * D_MODEL + d;
    for (int i = 0; i < 128; ++i) s += base[(long)i * D_MODEL];
    p[(b * 8 + cc) * D_MODEL + d] = s;
}

__global__ void __launch_bounds__(256)
pool2_kernel(const float* __restrict__ p, float* __restrict__ o)
{
    const int i = blockIdx.x * blockDim.x + threadIdx.x;
    const int b = i >> 9, d = i & 511;
    float s = 0.f;
#pragma unroll
    for (int cc = 0; cc < 8; ++cc) s += p[(b * 8 + cc) * D_MODEL + d];
    o[i] = s * (1.f / SEQ);
}

// ---------------------------------------------------------------------------
#define SMEM_BN128 (2 * (128 + 128) * 160)
#define SMEM_BN64  (2 * (128 +  64) * 160)

template<int BN, bool GEGLU>
static void launch_mg(const float* A, long lda, long aO, long aI,
                      const float* B, long ldb, long bO, long bI,
                      float* C, long ldc, long cO, long cI,
                      int M, int N, int K, int batches,
                      const float* bias, const float* resid,
                      const float* pos, float alpha)
{
    dim3 grid(N / BN, M / 128, batches);
    const int smem = (BN == 128) ? SMEM_BN128 : SMEM_BN64;
    mgemm_kernel<BN, GEGLU><<<grid, 256, smem>>>(A, lda, aO, aI, B, ldb, bO, bI,
                                                 C, ldc, cO, cI, K, bias, resid,
                                                 pos, alpha);
}

extern "C" void kernel_launch(void* const* d_in, const int* in_sizes, int n_in,
                              void* d_out, int out_size)
{
    const float* x      = (const float*)d_in[0];
    const float* proj_w = (const float*)d_in[1];
    const float* proj_b = (const float*)d_in[2];
    const float* pos    = (const float*)d_in[3];
    const float* ln1_g  = (const float*)d_in[4];
    const float* ln1_b  = (const float*)d_in[5];
    const float* wqkv   = (const float*)d_in[6];
    const float* wout   = (const float*)d_in[7];
    const float* bout   = (const float*)d_in[8];
    const float* ln2_g  = (const float*)d_in[9];
    const float* ln2_b  = (const float*)d_in[10];
    const float* w1     = (const float*)d_in[11];
    const float* b1     = (const float*)d_in[12];
    const float* w2     = (const float*)d_in[13];
    const float* b2     = (const float*)d_in[14];
    float* out = (float*)d_out;

    cudaFuncSetAttribute(mgemm_kernel<128, false>,
                         cudaFuncAttributeMaxDynamicSharedMemorySize, SMEM_BN128);
    cudaFuncSetAttribute(mgemm_kernel<128, true>,
                         cudaFuncAttributeMaxDynamicSharedMemorySize, SMEM_BN128);
    cudaFuncSetAttribute(mgemm_kernel<64, false>,
                         cudaFuncAttributeMaxDynamicSharedMemorySize, SMEM_BN64);

    float *gx, *gh, *gqkv, *gsim, *gao, *gffg, *gpool, *gwt, *gvt;
    cudaGetSymbolAddress((void**)&gx,    g_x);
    cudaGetSymbolAddress((void**)&gh,    g_h);
    cudaGetSymbolAddress((void**)&gqkv,  g_qkv);
    cudaGetSymbolAddress((void**)&gsim,  g_sim);
    cudaGetSymbolAddress((void**)&gao,   g_ao);
    cudaGetSymbolAddress((void**)&gffg,  g_ffg);
    cudaGetSymbolAddress((void**)&gpool, g_pool);
    cudaGetSymbolAddress((void**)&gwt,   g_wt);
    cudaGetSymbolAddress((void**)&gvt,   g_vt);

    // ---- weight transposes (B operands as [N,K] row-major) ----
    transpose_kernel<<<dim3(16, 16, 1), dim3(32, 8)>>>(
        proj_w, D_MODEL, 0, 0, gwt + OFF_PROJ, D_MODEL, 0, 0);
    transpose_kernel<<<dim3(48, 16, 3), dim3(32, 8)>>>(
        wqkv, 3 * D_MODEL, 0, (long)D_MODEL * 3 * D_MODEL,
        gwt + OFF_QKV, D_MODEL, 0, (long)3 * D_MODEL * D_MODEL);
    transpose_kernel<<<dim3(16, 16, 3), dim3(32, 8)>>>(
        wout, D_MODEL, 0, (long)D_MODEL * D_MODEL,
        gwt + OFF_WOUT, D_MODEL, 0, (long)D_MODEL * D_MODEL);
    transpose_w1_kernel<<<dim3(128, 16, 3), dim3(32, 8)>>>(w1, gwt + OFF_W1);
    transpose_kernel<<<dim3(16, 64, 3), dim3(32, 8)>>>(
        w2, D_MODEL, 0, (long)FF * D_MODEL,
        gwt + OFF_W2, FF, 0, (long)D_MODEL * FF);

    // x = x @ proj_w + proj_b + pos
    launch_mg<128, false>(x, D_MODEL, 0, 0, gwt + OFF_PROJ, D_MODEL, 0, 0,
                          gx, D_MODEL, 0, 0, NROWS, D_MODEL, D_MODEL, 1,
                          proj_b, nullptr, pos, 1.f);

    const float scale = 0.125f;

    for (int l = 0; l < NDEPTH; ++l) {
        ln_kernel<<<NROWS, 128>>>(gx, ln1_g + l * D_MODEL, ln1_b + l * D_MODEL, gh);

        // qkv = h @ Wqkv
        launch_mg<128, false>(gh, D_MODEL, 0, 0,
                              gwt + OFF_QKV + (long)l * 3 * D_MODEL * D_MODEL, D_MODEL, 0, 0,
                              gqkv, 3 * D_MODEL, 0, 0,
                              NROWS, 3 * D_MODEL, D_MODEL, 1, nullptr, nullptr, nullptr, 1.f);

        // V^T per (b,h): [1024,64] -> [64,1024]
        transpose_kernel<<<dim3(2, 32, NB * NHEADS), dim3(32, 8)>>>(
            gqkv + 2 * D_MODEL, 3 * D_MODEL, (long)SEQ * 3 * D_MODEL, DHEAD,
            gvt, SEQ, (long)NHEADS * DHEAD * SEQ, (long)DHEAD * SEQ);

        // sim = q @ k^T * scale
        launch_mg<128, false>(gqkv,           3 * D_MODEL, (long)SEQ * 3 * D_MODEL, DHEAD,
                              gqkv + D_MODEL, 3 * D_MODEL, (long)SEQ * 3 * D_MODEL, DHEAD,
                              gsim, SEQ, (long)NHEADS * SEQ * SEQ, (long)SEQ * SEQ,
                              SEQ, SEQ, DHEAD, NB * NHEADS,
                              nullptr, nullptr, nullptr, scale);

        sparsemax_kernel<<<NB * NHEADS * SEQ / 8, 256>>>(gsim);

        // ao = attn @ v
        launch_mg<64, false>(gsim, SEQ, (long)NHEADS * SEQ * SEQ, (long)SEQ * SEQ,
                             gvt,  SEQ, (long)NHEADS * DHEAD * SEQ, (long)DHEAD * SEQ,
                             gao, D_MODEL, (long)SEQ * D_MODEL, DHEAD,
                             SEQ, DHEAD, SEQ, NB * NHEADS,
                             nullptr, nullptr, nullptr, 1.f);

        // x = x + ao @ Wout + bout
        launch_mg<128, false>(gao, D_MODEL, 0, 0,
                              gwt + OFF_WOUT + (long)l * D_MODEL * D_MODEL, D_MODEL, 0, 0,
                              gx, D_MODEL, 0, 0, NROWS, D_MODEL, D_MODEL, 1,
                              bout + l * D_MODEL, gx, nullptr, 1.f);

        ln_kernel<<<NROWS, 128>>>(gx, ln2_g + l * D_MODEL, ln2_b + l * D_MODEL, gh);

        // ffg = GEGLU(h @ W1 + b1)   (fused epilogue; W1 interleaved a/g)
        launch_mg<128, true>(gh, D_MODEL, 0, 0,
                             gwt + OFF_W1 + (long)l * 2 * FF * D_MODEL, D_MODEL, 0, 0,
                             gffg, FF, 0, 0, NROWS, 2 * FF, D_MODEL, 1,
                             b1 + (long)l * 2 * FF, nullptr, nullptr, 1.f);

        // x = x + ffg @ W2 + b2
        launch_mg<128, false>(gffg, FF, 0, 0,
                              gwt + OFF_W2 + (long)l * D_MODEL * FF, FF, 0, 0,
                              gx, D_MODEL, 0, 0, NROWS, D_MODEL, FF, 1,
                              b2 + l * D_MODEL, gx, nullptr, 1.f);
    }

    pool1_kernel<<<dim3(NB, 8), 512>>>(gx, gpool);
    pool2_kernel<<<16, 256>>>(gpool, out);
}